// round 4
// baseline (speedup 1.0000x reference)
#include <cuda_runtime.h>
#include <cuda_bf16.h>
#include <cstdint>

// ---------------------------------------------------------------------------
// Shapes
// ---------------------------------------------------------------------------
#define BS      32
#define NUM_R   10
#define SL_Q    20
#define SL_H    40
#define WE      300
#define LSTM    1024
#define BILSTM  2048
#define FEATD   600   // 2*WE

// ---------------------------------------------------------------------------
// Scratch (device globals: no allocation allowed)
// ---------------------------------------------------------------------------
__device__ float g_qfeat[BS * SL_Q * LSTM];                 // 640 x 1024
__device__ float g_hfeat[BS * NUM_R * SL_H * LSTM];         // 12800 x 1024
__device__ float g_topic[BS * NUM_R * SL_Q * WE];           // scaled topic
__device__ float g_feat [BS * SL_Q * FEATD];                // 640 x 600

// ---------------------------------------------------------------------------
// tf32 helpers
// ---------------------------------------------------------------------------
__device__ __forceinline__ float tf32_rna(float x) {
    asm("cvt.rna.tf32.f32 %0, %0;" : "+f"(x));
    return x;
}

__device__ __forceinline__ void mma_tf32(float c[4], const uint32_t a[4],
                                         uint32_t b0, uint32_t b1) {
    asm volatile(
        "mma.sync.aligned.m16n8k8.row.col.f32.tf32.tf32.f32 "
        "{%0,%1,%2,%3},{%4,%5,%6,%7},{%8,%9},{%0,%1,%2,%3};"
        : "+f"(c[0]), "+f"(c[1]), "+f"(c[2]), "+f"(c[3])
        : "r"(a[0]), "r"(a[1]), "r"(a[2]), "r"(a[3]), "r"(b0), "r"(b1));
}

__device__ __forceinline__ float leaky(float x) {
    return x >= 0.f ? x : 0.01f * x;
}

// ---------------------------------------------------------------------------
// Kernel 1: gated transform  out = tanh(X@Wy + by) * leaky_relu(X@Wg + bg)
// X:[M,2048]  W:[2048,1024]  out:[M,1024]
// 3xTF32 split precision: a = a_hi + a_lo (each tf32); D = hh + hl + lh.
// Tile: BM=128 x BN=64, BK=32, 256 threads (8 warps, 4x2 warp grid, warp 32x32)
// ---------------------------------------------------------------------------
#define GK   BILSTM
#define GN   LSTM
#define BM   128
#define BN   64
#define BKD  32
#define BKP  36   // A smem row stride (floats): conflict-free frag loads
#define BNP  72   // B smem row stride (floats): conflict-free frag loads

#define A_TILE (BM * BKP)    // 4608 floats
#define B_TILE (BKD * BNP)   // 2304 floats
// smem: As_hi, As_lo, By_hi, By_lo, Bg_hi, Bg_lo
#define GG_SMEM_FLOATS (2 * A_TILE + 4 * B_TILE)   // 18432 floats = 73728 B

__global__ __launch_bounds__(256)
void gated_gemm(const float* __restrict__ X,
                const float* __restrict__ Wy, const float* __restrict__ by,
                const float* __restrict__ Wg, const float* __restrict__ bg,
                float* __restrict__ out) {
    extern __shared__ float sm[];
    float* As_hi = sm;
    float* As_lo = As_hi + A_TILE;
    float* By_hi = As_lo + A_TILE;
    float* By_lo = By_hi + B_TILE;
    float* Bg_hi = By_lo + B_TILE;
    float* Bg_lo = Bg_hi + B_TILE;

    const int tid  = threadIdx.x;
    const int warp = tid >> 5;
    const int lane = tid & 31;
    const int wm = (warp >> 1) * 32;  // warp M offset: 0,32,64,96
    const int wn = (warp & 1) * 32;   // warp N offset: 0,32
    const int m0 = blockIdx.x * BM;
    const int n0 = blockIdx.y * BN;

    const int ar = lane >> 2;   // frag row-in-8
    const int ac = lane & 3;    // frag k-in-4

    float accY[2][4][4];
    float accG[2][4][4];
#pragma unroll
    for (int mt = 0; mt < 2; mt++)
#pragma unroll
        for (int nt = 0; nt < 4; nt++)
#pragma unroll
            for (int i = 0; i < 4; i++) { accY[mt][nt][i] = 0.f; accG[mt][nt][i] = 0.f; }

    // global-load coordinates
    const int la_r = tid >> 3;            // 0..31
    const int la_c = (tid & 7) * 4;       // 0..28
    const int lb_r = tid >> 4;            // 0..15
    const int lb_c = (tid & 15) * 4;      // 0..60

    for (int kt = 0; kt < GK; kt += BKD) {
        // --- A tile: 128 x 32, split hi/lo ---
        {
            const float* gp = X + (size_t)m0 * GK + kt + la_c;
#pragma unroll
            for (int i = 0; i < 4; i++) {
                int r = la_r + 32 * i;
                float4 v = *(const float4*)(gp + (size_t)r * GK);
                float h0 = tf32_rna(v.x), h1 = tf32_rna(v.y);
                float h2 = tf32_rna(v.z), h3 = tf32_rna(v.w);
                As_hi[r * BKP + la_c + 0] = h0;
                As_hi[r * BKP + la_c + 1] = h1;
                As_hi[r * BKP + la_c + 2] = h2;
                As_hi[r * BKP + la_c + 3] = h3;
                As_lo[r * BKP + la_c + 0] = tf32_rna(v.x - h0);
                As_lo[r * BKP + la_c + 1] = tf32_rna(v.y - h1);
                As_lo[r * BKP + la_c + 2] = tf32_rna(v.z - h2);
                As_lo[r * BKP + la_c + 3] = tf32_rna(v.w - h3);
            }
        }
        // --- B tiles: 32 x 64 each, split hi/lo ---
        {
#pragma unroll
            for (int i = 0; i < 2; i++) {
                int kr = lb_r + 16 * i;
                float4 vy = *(const float4*)(Wy + (size_t)(kt + kr) * GN + n0 + lb_c);
                float4 vg = *(const float4*)(Wg + (size_t)(kt + kr) * GN + n0 + lb_c);
                float4 yh, yl, gh, gl;
                yh.x = tf32_rna(vy.x); yl.x = tf32_rna(vy.x - yh.x);
                yh.y = tf32_rna(vy.y); yl.y = tf32_rna(vy.y - yh.y);
                yh.z = tf32_rna(vy.z); yl.z = tf32_rna(vy.z - yh.z);
                yh.w = tf32_rna(vy.w); yl.w = tf32_rna(vy.w - yh.w);
                gh.x = tf32_rna(vg.x); gl.x = tf32_rna(vg.x - gh.x);
                gh.y = tf32_rna(vg.y); gl.y = tf32_rna(vg.y - gh.y);
                gh.z = tf32_rna(vg.z); gl.z = tf32_rna(vg.z - gh.z);
                gh.w = tf32_rna(vg.w); gl.w = tf32_rna(vg.w - gh.w);
                *(float4*)&By_hi[kr * BNP + lb_c] = yh;
                *(float4*)&By_lo[kr * BNP + lb_c] = yl;
                *(float4*)&Bg_hi[kr * BNP + lb_c] = gh;
                *(float4*)&Bg_lo[kr * BNP + lb_c] = gl;
            }
        }
        __syncthreads();

#pragma unroll
        for (int ks = 0; ks < BKD; ks += 8) {
            uint32_t ah[2][4], al[2][4];
#pragma unroll
            for (int mt = 0; mt < 2; mt++) {
                int rb = wm + mt * 16;
                int o0 = (rb + ar)     * BKP + ks + ac;
                int o1 = (rb + ar + 8) * BKP + ks + ac;
                ah[mt][0] = __float_as_uint(As_hi[o0]);
                ah[mt][1] = __float_as_uint(As_hi[o1]);
                ah[mt][2] = __float_as_uint(As_hi[o0 + 4]);
                ah[mt][3] = __float_as_uint(As_hi[o1 + 4]);
                al[mt][0] = __float_as_uint(As_lo[o0]);
                al[mt][1] = __float_as_uint(As_lo[o1]);
                al[mt][2] = __float_as_uint(As_lo[o0 + 4]);
                al[mt][3] = __float_as_uint(As_lo[o1 + 4]);
            }
#pragma unroll
            for (int nt = 0; nt < 4; nt++) {
                int nb = wn + nt * 8 + (lane >> 2);
                int k0 = ks + (lane & 3);
                int ob0 = k0       * BNP + nb;
                int ob1 = (k0 + 4) * BNP + nb;
                uint32_t byh0 = __float_as_uint(By_hi[ob0]);
                uint32_t byh1 = __float_as_uint(By_hi[ob1]);
                uint32_t byl0 = __float_as_uint(By_lo[ob0]);
                uint32_t byl1 = __float_as_uint(By_lo[ob1]);
                uint32_t bgh0 = __float_as_uint(Bg_hi[ob0]);
                uint32_t bgh1 = __float_as_uint(Bg_hi[ob1]);
                uint32_t bgl0 = __float_as_uint(Bg_lo[ob0]);
                uint32_t bgl1 = __float_as_uint(Bg_lo[ob1]);
#pragma unroll
                for (int mt = 0; mt < 2; mt++) {
                    // 3xTF32: hi*hi + hi*lo + lo*hi
                    mma_tf32(accY[mt][nt], al[mt], byh0, byh1);
                    mma_tf32(accY[mt][nt], ah[mt], byl0, byl1);
                    mma_tf32(accY[mt][nt], ah[mt], byh0, byh1);
                    mma_tf32(accG[mt][nt], al[mt], bgh0, bgh1);
                    mma_tf32(accG[mt][nt], ah[mt], bgl0, bgl1);
                    mma_tf32(accG[mt][nt], ah[mt], bgh0, bgh1);
                }
            }
        }
        __syncthreads();
    }

    // epilogue: bias + tanh * leaky_relu
#pragma unroll
    for (int mt = 0; mt < 2; mt++) {
#pragma unroll
        for (int nt = 0; nt < 4; nt++) {
            int gr = m0 + wm + mt * 16 + ar;
            int gc = n0 + wn + nt * 8 + (lane & 3) * 2;
            float b_y0 = by[gc], b_y1 = by[gc + 1];
            float b_g0 = bg[gc], b_g1 = bg[gc + 1];

            float v00 = tanhf(accY[mt][nt][0] + b_y0) * leaky(accG[mt][nt][0] + b_g0);
            float v01 = tanhf(accY[mt][nt][1] + b_y1) * leaky(accG[mt][nt][1] + b_g1);
            float v10 = tanhf(accY[mt][nt][2] + b_y0) * leaky(accG[mt][nt][2] + b_g0);
            float v11 = tanhf(accY[mt][nt][3] + b_y1) * leaky(accG[mt][nt][3] + b_g1);

            *(float2*)&out[(size_t)gr * GN + gc]       = make_float2(v00, v01);
            *(float2*)&out[(size_t)(gr + 8) * GN + gc] = make_float2(v10, v11);
        }
    }
}

// ---------------------------------------------------------------------------
// Kernel 2: per-(b,r) attention block
//   score[q,h] = dot(q_feat[b,q,:], h_feat[b,r,h,:])  (K=1024)
//   mask, softmax over h, topic = att @ emb, scaled by cms -> g_topic
// block: (r, b); 256 threads; dynamic smem
// ---------------------------------------------------------------------------
#define CK 64
#define QS_STRIDE 65
#define HS_STRIDE 65
// smem floats: emb 12000 | qs 20*65 | hs 40*65 | S 800
#define ATTN_SMEM_FLOATS (12000 + SL_Q * QS_STRIDE + SL_H * HS_STRIDE + SL_Q * SL_H)

__global__ __launch_bounds__(256)
void attn_kernel(const float* __restrict__ qf, const float* __restrict__ hf,
                 const float* __restrict__ emb, const float* __restrict__ notpad,
                 const float* __restrict__ cms, float* __restrict__ topic) {
    extern __shared__ float sm[];
    float* emb_s = sm;
    float* qs = emb_s + 12000;
    float* hs = qs + SL_Q * QS_STRIDE;
    float* S  = hs + SL_H * HS_STRIDE;

    const int t = threadIdx.x;
    const int r = blockIdx.x;
    const int b = blockIdx.y;
    const int br = b * NUM_R + r;

    // load embedding tile (40x300) once
    for (int i = t; i < SL_H * WE; i += 256)
        emb_s[i] = emb[(size_t)br * (SL_H * WE) + i];

    // 2x2 register tile over the 20x40 score matrix (200 active threads)
    const int q2 = t / 20;   // 0..9  (valid when t<200)
    const int h2 = t % 20;   // 0..19
    float acc00 = 0.f, acc01 = 0.f, acc10 = 0.f, acc11 = 0.f;

    for (int kc = 0; kc < LSTM; kc += CK) {
        for (int i = t; i < SL_Q * CK; i += 256) {
            int row = i >> 6, col = i & 63;
            qs[row * QS_STRIDE + col] = qf[(size_t)(b * SL_Q + row) * LSTM + kc + col];
        }
        for (int i = t; i < SL_H * CK; i += 256) {
            int row = i >> 6, col = i & 63;
            hs[row * HS_STRIDE + col] = hf[(size_t)(br * SL_H + row) * LSTM + kc + col];
        }
        __syncthreads();
        if (t < 200) {
            const float* q0p = &qs[(2 * q2)     * QS_STRIDE];
            const float* q1p = &qs[(2 * q2 + 1) * QS_STRIDE];
            const float* h0p = &hs[(2 * h2)     * HS_STRIDE];
            const float* h1p = &hs[(2 * h2 + 1) * HS_STRIDE];
#pragma unroll 8
            for (int k = 0; k < CK; k++) {
                float q0 = q0p[k], q1 = q1p[k];
                float h0 = h0p[k], h1 = h1p[k];
                acc00 += q0 * h0; acc01 += q0 * h1;
                acc10 += q1 * h0; acc11 += q1 * h1;
            }
        }
        __syncthreads();
    }

    if (t < 200) {
        S[(2 * q2)     * SL_H + 2 * h2]     = acc00;
        S[(2 * q2)     * SL_H + 2 * h2 + 1] = acc01;
        S[(2 * q2 + 1) * SL_H + 2 * h2]     = acc10;
        S[(2 * q2 + 1) * SL_H + 2 * h2 + 1] = acc11;
    }
    __syncthreads();

    // mask + softmax over h (rows handled by threads 0..19)
    if (t < SL_Q) {
        float mx = -1e30f;
        for (int h = 0; h < SL_H; h++) {
            float m = notpad[(size_t)br * SL_H + h];
            float s = S[t * SL_H + h] * m + (m - 1.0f) * 10000.0f;
            S[t * SL_H + h] = s;
            mx = fmaxf(mx, s);
        }
        float den = 0.f;
        for (int h = 0; h < SL_H; h++) {
            float e = expf(S[t * SL_H + h] - mx);
            S[t * SL_H + h] = e;
            den += e;
        }
        float inv = 1.0f / den;
        for (int h = 0; h < SL_H; h++) S[t * SL_H + h] *= inv;
    }
    __syncthreads();

    // topic = att @ emb, scaled by cms, write scratch
    const float c = cms[br];
    for (int o = t; o < SL_Q * WE; o += 256) {
        int q = o / WE, e = o % WE;
        float s = 0.f;
#pragma unroll 8
        for (int h = 0; h < SL_H; h++)
            s += S[q * SL_H + h] * emb_s[h * WE + e];
        topic[(size_t)(br * SL_Q + q) * WE + e] = s * c;
    }
}

// ---------------------------------------------------------------------------
// Kernel 3: feat = concat(q_embed, sum_r topic)  -> [640, 600]
// ---------------------------------------------------------------------------
__global__ __launch_bounds__(256)
void feat_build(const float* __restrict__ q_embed, const float* __restrict__ topic,
                float* __restrict__ feat) {
    int idx = blockIdx.x * 256 + threadIdx.x;   // 0 .. 383999
    int m  = idx / FEATD;                       // b*20+q
    int e2 = idx % FEATD;
    float v;
    if (e2 < WE) {
        v = q_embed[(size_t)m * WE + e2];
    } else {
        int e = e2 - WE;
        int b = m / SL_Q, q = m % SL_Q;
        v = 0.f;
#pragma unroll
        for (int r = 0; r < NUM_R; r++)
            v += topic[(size_t)((b * NUM_R + r) * SL_Q + q) * WE + e];
    }
    feat[idx] = v;
}

// ---------------------------------------------------------------------------
// Kernel 4: out = sigmoid(feat@Wg + bg) * feat    M=640 K=600 N=600
// ---------------------------------------------------------------------------
#define FBM 64
#define FBN 64
#define FBK 16

__global__ __launch_bounds__(256)
void final_gemm(const float* __restrict__ feat, const float* __restrict__ Wg,
                const float* __restrict__ bg, float* __restrict__ out) {
    __shared__ float Fs[FBM][FBK + 1];
    __shared__ float Bs[FBK][FBN + 1];

    const int t = threadIdx.x;
    const int ty = t >> 4, tx = t & 15;
    const int m0 = blockIdx.x * FBM;
    const int n0 = blockIdx.y * FBN;

    float acc[4][4];
#pragma unroll
    for (int i = 0; i < 4; i++)
#pragma unroll
        for (int j = 0; j < 4; j++) acc[i][j] = 0.f;

    for (int k0 = 0; k0 < FEATD; k0 += FBK) {
        for (int i = t; i < FBM * FBK; i += 256) {
            int r = i >> 4, c = i & 15;
            int k = k0 + c;
            Fs[r][c] = (k < FEATD) ? feat[(size_t)(m0 + r) * FEATD + k] : 0.f;
        }
        for (int i = t; i < FBK * FBN; i += 256) {
            int r = i >> 6, c = i & 63;
            int k = k0 + r, n = n0 + c;
            Bs[r][c] = (k < FEATD && n < FEATD) ? Wg[(size_t)k * FEATD + n] : 0.f;
        }
        __syncthreads();
#pragma unroll
        for (int k = 0; k < FBK; k++) {
            float a[4], bb[4];
#pragma unroll
            for (int i = 0; i < 4; i++) a[i]  = Fs[ty * 4 + i][k];
#pragma unroll
            for (int j = 0; j < 4; j++) bb[j] = Bs[k][tx * 4 + j];
#pragma unroll
            for (int i = 0; i < 4; i++)
#pragma unroll
                for (int j = 0; j < 4; j++) acc[i][j] += a[i] * bb[j];
        }
        __syncthreads();
    }

#pragma unroll
    for (int i = 0; i < 4; i++) {
        int row = m0 + ty * 4 + i;
#pragma unroll
        for (int j = 0; j < 4; j++) {
            int col = n0 + tx * 4 + j;
            if (col < FEATD) {
                float v = acc[i][j] + bg[col];
                float g = 1.0f / (1.0f + expf(-v));
                out[(size_t)row * FEATD + col] = g * feat[(size_t)row * FEATD + col];
            }
        }
    }
}

// ---------------------------------------------------------------------------
// Host launcher
// ---------------------------------------------------------------------------
extern "C" void kernel_launch(void* const* d_in, const int* in_sizes, int n_in,
                              void* d_out, int out_size) {
    const float* q_embed = (const float*)d_in[0];
    const float* q_enc   = (const float*)d_in[1];
    const float* h_embed = (const float*)d_in[2];
    const float* h_enc   = (const float*)d_in[3];
    const float* notpad  = (const float*)d_in[4];
    const float* cms     = (const float*)d_in[5];
    const float* Wq_y = (const float*)d_in[6];
    const float* bq_y = (const float*)d_in[7];
    const float* Wq_g = (const float*)d_in[8];
    const float* bq_g = (const float*)d_in[9];
    const float* Wh_y = (const float*)d_in[10];
    const float* bh_y = (const float*)d_in[11];
    const float* Wh_g = (const float*)d_in[12];
    const float* bh_g = (const float*)d_in[13];
    const float* Wg   = (const float*)d_in[14];
    const float* bg   = (const float*)d_in[15];
    float* out = (float*)d_out;

    float *qf, *hf, *topic, *feat;
    cudaGetSymbolAddress((void**)&qf,    g_qfeat);
    cudaGetSymbolAddress((void**)&hf,    g_hfeat);
    cudaGetSymbolAddress((void**)&topic, g_topic);
    cudaGetSymbolAddress((void**)&feat,  g_feat);

    const int gg_smem = GG_SMEM_FLOATS * (int)sizeof(float);   // 73728 B
    cudaFuncSetAttribute(gated_gemm, cudaFuncAttributeMaxDynamicSharedMemorySize,
                         gg_smem);
    const int attn_smem = ATTN_SMEM_FLOATS * (int)sizeof(float);
    cudaFuncSetAttribute(attn_kernel, cudaFuncAttributeMaxDynamicSharedMemorySize,
                         attn_smem);

    // gated transforms (3xTF32 tensor-core GEMMs)
    gated_gemm<<<dim3((BS * SL_Q) / BM, GN / BN), 256, gg_smem>>>(q_enc, Wq_y, bq_y, Wq_g, bq_g, qf);
    gated_gemm<<<dim3((BS * NUM_R * SL_H) / BM, GN / BN), 256, gg_smem>>>(h_enc, Wh_y, bh_y, Wh_g, bh_g, hf);

    // per-(b,r) attention + topic
    attn_kernel<<<dim3(NUM_R, BS), 256, attn_smem>>>(qf, hf, h_embed, notpad, cms, topic);

    // concat + reduce over r
    feat_build<<<(BS * SL_Q * FEATD) / 256, 256>>>(q_embed, topic, feat);

    // final gated output
    final_gemm<<<dim3((BS * SL_Q) / FBM, (FEATD + FBN - 1) / FBN), 256>>>(feat, Wg, bg, out);
}

// round 5
// speedup vs baseline: 1.6775x; 1.6775x over previous
#include <cuda_runtime.h>
#include <cuda_bf16.h>
#include <cstdint>

// ---------------------------------------------------------------------------
// Shapes
// ---------------------------------------------------------------------------
#define BS      32
#define NUM_R   10
#define SL_Q    20
#define SL_H    40
#define WE      300
#define LSTM    1024
#define BILSTM  2048
#define FEATD   600   // 2*WE

// ---------------------------------------------------------------------------
// Scratch (device globals: no allocation allowed)
// ---------------------------------------------------------------------------
__device__ float g_qfeat[BS * SL_Q * LSTM];                 // 640 x 1024
__device__ float g_hfeat[BS * NUM_R * SL_H * LSTM];         // 12800 x 1024
__device__ float g_topic[BS * NUM_R * SL_Q * WE];           // scaled topic
__device__ float g_feat [BS * SL_Q * FEATD];                // 640 x 600

// ---------------------------------------------------------------------------
// bf16 split helpers
// ---------------------------------------------------------------------------
__device__ __forceinline__ void split_pair(float x, float y,
                                           uint32_t& hi, uint32_t& lo) {
    __nv_bfloat16 bx = __float2bfloat16(x);
    __nv_bfloat16 by = __float2bfloat16(y);
    float rx = x - __bfloat162float(bx);
    float ry = y - __bfloat162float(by);
    __nv_bfloat162 h2; h2.x = bx; h2.y = by;
    __nv_bfloat162 l2 = __floats2bfloat162_rn(rx, ry);
    hi = *reinterpret_cast<uint32_t*>(&h2);
    lo = *reinterpret_cast<uint32_t*>(&l2);
}

__device__ __forceinline__ void mma_bf16(float c[4], const uint32_t a[4],
                                         uint32_t b0, uint32_t b1) {
    asm volatile(
        "mma.sync.aligned.m16n8k16.row.col.f32.bf16.bf16.f32 "
        "{%0,%1,%2,%3},{%4,%5,%6,%7},{%8,%9},{%0,%1,%2,%3};"
        : "+f"(c[0]), "+f"(c[1]), "+f"(c[2]), "+f"(c[3])
        : "r"(a[0]), "r"(a[1]), "r"(a[2]), "r"(a[3]), "r"(b0), "r"(b1));
}

__device__ __forceinline__ float leaky(float x) {
    return x >= 0.f ? x : 0.01f * x;
}

// ---------------------------------------------------------------------------
// Kernel 1: gated transform  out = tanh(X@Wy + by) * leaky_relu(X@Wg + bg)
// X:[M,2048]  W:[2048,1024]  out:[M,1024]
// 3xBF16 split precision: a = a_hi + a_lo (bf16); D = hh + hl + lh.
// Tile: BM=128 x BN=64, BK=32, 256 threads, 8 warps (4m x 2n), warp 32x32.
// Double-buffered smem, one __syncthreads per K-chunk.
// smem stores PACKED bf16x2 k-pairs as uint32:
//   A: [m][kpair]  stride RA=20 words  (conflict-free frag loads: 4m+kp mod 32)
//   B: [kpair][n]  stride RB=72 words  (conflict-free frag loads: 8kp+n mod 32)
// ---------------------------------------------------------------------------
#define GK   BILSTM
#define GN   LSTM
#define BM   128
#define BN   64
#define BKD  32
#define KPAIRS (BKD / 2)          // 16 k-pairs per chunk
#define RA   20                   // A row stride (words)
#define RB   72                   // B row stride (words)
#define A_PART (BM * RA)          // 2560 words
#define B_PART (KPAIRS * RB)      // 1152 words
#define BUF_WORDS (2 * A_PART + 4 * B_PART)   // 9728 words
#define GG_SMEM_BYTES (2 * BUF_WORDS * 4)     // 77824 B

__global__ __launch_bounds__(256, 2)
void gated_gemm(const float* __restrict__ X,
                const float* __restrict__ Wy, const float* __restrict__ by,
                const float* __restrict__ Wg, const float* __restrict__ bg,
                float* __restrict__ out) {
    extern __shared__ uint32_t smw[];

    const int tid  = threadIdx.x;
    const int warp = tid >> 5;
    const int lane = tid & 31;
    const int wm = (warp >> 1) * 32;  // warp M offset: 0,32,64,96
    const int wn = (warp & 1) * 32;   // warp N offset: 0,32
    const int m0 = blockIdx.x * BM;
    const int n0 = blockIdx.y * BN;

    const int ar = lane >> 2;   // frag row-in-8
    const int ac = lane & 3;    // frag kpair-in-4

    float accY[2][4][4] = {};
    float accG[2][4][4] = {};

    // global-load coordinates
    const int a_r  = tid >> 3;            // 0..31 (+32*i)
    const int a_c  = (tid & 7) * 4;       // f32 k-col 0..28
    const int b_kr = 2 * (tid >> 4);      // k row base 0,2,..,30
    const int b_n  = 4 * (tid & 15);      // n col 0..60

    const float* Ag = X  + (size_t)(m0 + a_r) * GK + a_c;
    const float* Yg = Wy + (size_t)b_kr * GN + n0 + b_n;
    const float* Gg = Wg + (size_t)b_kr * GN + n0 + b_n;

    float4 av[4], yv0, yv1, gv0, gv1;

    // --- prefetch tile kt into registers ---
    auto ldg_tile = [&](int kt) {
#pragma unroll
        for (int i = 0; i < 4; i++)
            av[i] = *(const float4*)(Ag + (size_t)(32 * i) * GK + kt);
        yv0 = *(const float4*)(Yg + (size_t)kt * GN);
        yv1 = *(const float4*)(Yg + (size_t)(kt + 1) * GN);
        gv0 = *(const float4*)(Gg + (size_t)kt * GN);
        gv1 = *(const float4*)(Gg + (size_t)(kt + 1) * GN);
    };

    // --- convert + store registers into smem buffer ---
    auto sts_tile = [&](int buf) {
        uint32_t* base = smw + buf * BUF_WORDS;
        uint32_t* Ah  = base;
        uint32_t* Al  = base + A_PART;
        uint32_t* Byh = base + 2 * A_PART;
        uint32_t* Byl = Byh + B_PART;
        uint32_t* Bgh = Byl + B_PART;
        uint32_t* Bgl = Bgh + B_PART;

        const int kp0 = a_c >> 1;
#pragma unroll
        for (int i = 0; i < 4; i++) {
            int r = a_r + 32 * i;
            uint32_t h0, l0, h1, l1;
            split_pair(av[i].x, av[i].y, h0, l0);
            split_pair(av[i].z, av[i].w, h1, l1);
            *(uint2*)&Ah[r * RA + kp0] = make_uint2(h0, h1);
            *(uint2*)&Al[r * RA + kp0] = make_uint2(l0, l1);
        }
        const int kp = tid >> 4;
        {
            uint32_t h[4], l[4];
            split_pair(yv0.x, yv1.x, h[0], l[0]);
            split_pair(yv0.y, yv1.y, h[1], l[1]);
            split_pair(yv0.z, yv1.z, h[2], l[2]);
            split_pair(yv0.w, yv1.w, h[3], l[3]);
            *(uint4*)&Byh[kp * RB + b_n] = make_uint4(h[0], h[1], h[2], h[3]);
            *(uint4*)&Byl[kp * RB + b_n] = make_uint4(l[0], l[1], l[2], l[3]);
        }
        {
            uint32_t h[4], l[4];
            split_pair(gv0.x, gv1.x, h[0], l[0]);
            split_pair(gv0.y, gv1.y, h[1], l[1]);
            split_pair(gv0.z, gv1.z, h[2], l[2]);
            split_pair(gv0.w, gv1.w, h[3], l[3]);
            *(uint4*)&Bgh[kp * RB + b_n] = make_uint4(h[0], h[1], h[2], h[3]);
            *(uint4*)&Bgl[kp * RB + b_n] = make_uint4(l[0], l[1], l[2], l[3]);
        }
    };

    // --- consume one smem buffer: 2 k-steps of m16n8k16 ---
    auto compute = [&](int buf) {
        const uint32_t* base = smw + buf * BUF_WORDS;
        const uint32_t* Ah  = base;
        const uint32_t* Al  = base + A_PART;
        const uint32_t* Byh = base + 2 * A_PART;
        const uint32_t* Byl = Byh + B_PART;
        const uint32_t* Bgh = Byl + B_PART;
        const uint32_t* Bgl = Bgh + B_PART;

#pragma unroll
        for (int ks = 0; ks < 2; ks++) {
            const int kpb = 8 * ks;
            uint32_t ah[2][4], al[2][4];
#pragma unroll
            for (int mt = 0; mt < 2; mt++) {
                int r0 = wm + 16 * mt + ar;
                int o0 = r0 * RA + kpb + ac;
                int o1 = (r0 + 8) * RA + kpb + ac;
                ah[mt][0] = Ah[o0];
                ah[mt][1] = Ah[o1];
                ah[mt][2] = Ah[o0 + 4];
                ah[mt][3] = Ah[o1 + 4];
                al[mt][0] = Al[o0];
                al[mt][1] = Al[o1];
                al[mt][2] = Al[o0 + 4];
                al[mt][3] = Al[o1 + 4];
            }
#pragma unroll
            for (int nt = 0; nt < 4; nt++) {
                int n  = wn + 8 * nt + (lane >> 2);
                int o0 = (kpb + ac) * RB + n;
                int o1 = (kpb + ac + 4) * RB + n;
                uint32_t byh0 = Byh[o0], byh1 = Byh[o1];
                uint32_t byl0 = Byl[o0], byl1 = Byl[o1];
                uint32_t bgh0 = Bgh[o0], bgh1 = Bgh[o1];
                uint32_t bgl0 = Bgl[o0], bgl1 = Bgl[o1];
#pragma unroll
                for (int mt = 0; mt < 2; mt++) {
                    mma_bf16(accY[mt][nt], al[mt], byh0, byh1);
                    mma_bf16(accY[mt][nt], ah[mt], byl0, byl1);
                    mma_bf16(accY[mt][nt], ah[mt], byh0, byh1);
                    mma_bf16(accG[mt][nt], al[mt], bgh0, bgh1);
                    mma_bf16(accG[mt][nt], ah[mt], bgl0, bgl1);
                    mma_bf16(accG[mt][nt], ah[mt], bgh0, bgh1);
                }
            }
        }
    };

    // --- main loop: double-buffered, one sync per chunk ---
    ldg_tile(0);
    sts_tile(0);
    __syncthreads();
    int buf = 0;
    for (int kt = 0; kt < GK; kt += BKD) {
        bool last = (kt + BKD >= GK);
        if (!last) ldg_tile(kt + BKD);
        compute(buf);
        if (!last) {
            sts_tile(buf ^ 1);
            __syncthreads();
            buf ^= 1;
        }
    }

    // epilogue: bias + tanh * leaky_relu
#pragma unroll
    for (int mt = 0; mt < 2; mt++) {
#pragma unroll
        for (int nt = 0; nt < 4; nt++) {
            int gr = m0 + wm + mt * 16 + ar;
            int gc = n0 + wn + nt * 8 + (lane & 3) * 2;
            float b_y0 = by[gc], b_y1 = by[gc + 1];
            float b_g0 = bg[gc], b_g1 = bg[gc + 1];

            float v00 = tanhf(accY[mt][nt][0] + b_y0) * leaky(accG[mt][nt][0] + b_g0);
            float v01 = tanhf(accY[mt][nt][1] + b_y1) * leaky(accG[mt][nt][1] + b_g1);
            float v10 = tanhf(accY[mt][nt][2] + b_y0) * leaky(accG[mt][nt][2] + b_g0);
            float v11 = tanhf(accY[mt][nt][3] + b_y1) * leaky(accG[mt][nt][3] + b_g1);

            *(float2*)&out[(size_t)gr * GN + gc]       = make_float2(v00, v01);
            *(float2*)&out[(size_t)(gr + 8) * GN + gc] = make_float2(v10, v11);
        }
    }
}

// ---------------------------------------------------------------------------
// Kernel 2: per-(b,r) attention block
//   score[q,h] = dot(q_feat[b,q,:], h_feat[b,r,h,:])  (K=1024)
//   mask, softmax over h, topic = att @ emb, scaled by cms -> g_topic
// block: (r, b); 256 threads; dynamic smem
// ---------------------------------------------------------------------------
#define CK 64
#define QS_STRIDE 65
#define HS_STRIDE 65
// smem floats: emb 12000 | qs 20*65 | hs 40*65 | S 800
#define ATTN_SMEM_FLOATS (12000 + SL_Q * QS_STRIDE + SL_H * HS_STRIDE + SL_Q * SL_H)

__global__ __launch_bounds__(256)
void attn_kernel(const float* __restrict__ qf, const float* __restrict__ hf,
                 const float* __restrict__ emb, const float* __restrict__ notpad,
                 const float* __restrict__ cms, float* __restrict__ topic) {
    extern __shared__ float sm[];
    float* emb_s = sm;
    float* qs = emb_s + 12000;
    float* hs = qs + SL_Q * QS_STRIDE;
    float* S  = hs + SL_H * HS_STRIDE;

    const int t = threadIdx.x;
    const int r = blockIdx.x;
    const int b = blockIdx.y;
    const int br = b * NUM_R + r;

    // load embedding tile (40x300) once
    for (int i = t; i < SL_H * WE; i += 256)
        emb_s[i] = emb[(size_t)br * (SL_H * WE) + i];

    // 2x2 register tile over the 20x40 score matrix (200 active threads)
    const int q2 = t / 20;   // 0..9  (valid when t<200)
    const int h2 = t % 20;   // 0..19
    float acc00 = 0.f, acc01 = 0.f, acc10 = 0.f, acc11 = 0.f;

    for (int kc = 0; kc < LSTM; kc += CK) {
        for (int i = t; i < SL_Q * CK; i += 256) {
            int row = i >> 6, col = i & 63;
            qs[row * QS_STRIDE + col] = qf[(size_t)(b * SL_Q + row) * LSTM + kc + col];
        }
        for (int i = t; i < SL_H * CK; i += 256) {
            int row = i >> 6, col = i & 63;
            hs[row * HS_STRIDE + col] = hf[(size_t)(br * SL_H + row) * LSTM + kc + col];
        }
        __syncthreads();
        if (t < 200) {
            const float* q0p = &qs[(2 * q2)     * QS_STRIDE];
            const float* q1p = &qs[(2 * q2 + 1) * QS_STRIDE];
            const float* h0p = &hs[(2 * h2)     * HS_STRIDE];
            const float* h1p = &hs[(2 * h2 + 1) * HS_STRIDE];
#pragma unroll 8
            for (int k = 0; k < CK; k++) {
                float q0 = q0p[k], q1 = q1p[k];
                float h0 = h0p[k], h1 = h1p[k];
                acc00 += q0 * h0; acc01 += q0 * h1;
                acc10 += q1 * h0; acc11 += q1 * h1;
            }
        }
        __syncthreads();
    }

    if (t < 200) {
        S[(2 * q2)     * SL_H + 2 * h2]     = acc00;
        S[(2 * q2)     * SL_H + 2 * h2 + 1] = acc01;
        S[(2 * q2 + 1) * SL_H + 2 * h2]     = acc10;
        S[(2 * q2 + 1) * SL_H + 2 * h2 + 1] = acc11;
    }
    __syncthreads();

    // mask + softmax over h (rows handled by threads 0..19)
    if (t < SL_Q) {
        float mx = -1e30f;
        for (int h = 0; h < SL_H; h++) {
            float m = notpad[(size_t)br * SL_H + h];
            float s = S[t * SL_H + h] * m + (m - 1.0f) * 10000.0f;
            S[t * SL_H + h] = s;
            mx = fmaxf(mx, s);
        }
        float den = 0.f;
        for (int h = 0; h < SL_H; h++) {
            float e = expf(S[t * SL_H + h] - mx);
            S[t * SL_H + h] = e;
            den += e;
        }
        float inv = 1.0f / den;
        for (int h = 0; h < SL_H; h++) S[t * SL_H + h] *= inv;
    }
    __syncthreads();

    // topic = att @ emb, scaled by cms, write scratch
    const float c = cms[br];
    for (int o = t; o < SL_Q * WE; o += 256) {
        int q = o / WE, e = o % WE;
        float s = 0.f;
#pragma unroll 8
        for (int h = 0; h < SL_H; h++)
            s += S[q * SL_H + h] * emb_s[h * WE + e];
        topic[(size_t)(br * SL_Q + q) * WE + e] = s * c;
    }
}

// ---------------------------------------------------------------------------
// Kernel 3: feat = concat(q_embed, sum_r topic)  -> [640, 600]
// ---------------------------------------------------------------------------
__global__ __launch_bounds__(256)
void feat_build(const float* __restrict__ q_embed, const float* __restrict__ topic,
                float* __restrict__ feat) {
    int idx = blockIdx.x * 256 + threadIdx.x;   // 0 .. 383999
    int m  = idx / FEATD;                       // b*20+q
    int e2 = idx % FEATD;
    float v;
    if (e2 < WE) {
        v = q_embed[(size_t)m * WE + e2];
    } else {
        int e = e2 - WE;
        int b = m / SL_Q, q = m % SL_Q;
        v = 0.f;
#pragma unroll
        for (int r = 0; r < NUM_R; r++)
            v += topic[(size_t)((b * NUM_R + r) * SL_Q + q) * WE + e];
    }
    feat[idx] = v;
}

// ---------------------------------------------------------------------------
// Kernel 4: out = sigmoid(feat@Wg + bg) * feat    M=640 K=600 N=600
// ---------------------------------------------------------------------------
#define FBM 64
#define FBN 64
#define FBK 16

__global__ __launch_bounds__(256)
void final_gemm(const float* __restrict__ feat, const float* __restrict__ Wg,
                const float* __restrict__ bg, float* __restrict__ out) {
    __shared__ float Fs[FBM][FBK + 1];
    __shared__ float Bs[FBK][FBN + 1];

    const int t = threadIdx.x;
    const int ty = t >> 4, tx = t & 15;
    const int m0 = blockIdx.x * FBM;
    const int n0 = blockIdx.y * FBN;

    float acc[4][4];
#pragma unroll
    for (int i = 0; i < 4; i++)
#pragma unroll
        for (int j = 0; j < 4; j++) acc[i][j] = 0.f;

    for (int k0 = 0; k0 < FEATD; k0 += FBK) {
        for (int i = t; i < FBM * FBK; i += 256) {
            int r = i >> 4, c = i & 15;
            int k = k0 + c;
            Fs[r][c] = (k < FEATD) ? feat[(size_t)(m0 + r) * FEATD + k] : 0.f;
        }
        for (int i = t; i < FBK * FBN; i += 256) {
            int r = i >> 6, c = i & 63;
            int k = k0 + r, n = n0 + c;
            Bs[r][c] = (k < FEATD && n < FEATD) ? Wg[(size_t)k * FEATD + n] : 0.f;
        }
        __syncthreads();
#pragma unroll
        for (int k = 0; k < FBK; k++) {
            float a[4], bb[4];
#pragma unroll
            for (int i = 0; i < 4; i++) a[i]  = Fs[ty * 4 + i][k];
#pragma unroll
            for (int j = 0; j < 4; j++) bb[j] = Bs[k][tx * 4 + j];
#pragma unroll
            for (int i = 0; i < 4; i++)
#pragma unroll
                for (int j = 0; j < 4; j++) acc[i][j] += a[i] * bb[j];
        }
        __syncthreads();
    }

#pragma unroll
    for (int i = 0; i < 4; i++) {
        int row = m0 + ty * 4 + i;
#pragma unroll
        for (int j = 0; j < 4; j++) {
            int col = n0 + tx * 4 + j;
            if (col < FEATD) {
                float v = acc[i][j] + bg[col];
                float g = 1.0f / (1.0f + expf(-v));
                out[(size_t)row * FEATD + col] = g * feat[(size_t)row * FEATD + col];
            }
        }
    }
}

// ---------------------------------------------------------------------------
// Host launcher
// ---------------------------------------------------------------------------
extern "C" void kernel_launch(void* const* d_in, const int* in_sizes, int n_in,
                              void* d_out, int out_size) {
    const float* q_embed = (const float*)d_in[0];
    const float* q_enc   = (const float*)d_in[1];
    const float* h_embed = (const float*)d_in[2];
    const float* h_enc   = (const float*)d_in[3];
    const float* notpad  = (const float*)d_in[4];
    const float* cms     = (const float*)d_in[5];
    const float* Wq_y = (const float*)d_in[6];
    const float* bq_y = (const float*)d_in[7];
    const float* Wq_g = (const float*)d_in[8];
    const float* bq_g = (const float*)d_in[9];
    const float* Wh_y = (const float*)d_in[10];
    const float* bh_y = (const float*)d_in[11];
    const float* Wh_g = (const float*)d_in[12];
    const float* bh_g = (const float*)d_in[13];
    const float* Wg   = (const float*)d_in[14];
    const float* bg   = (const float*)d_in[15];
    float* out = (float*)d_out;

    float *qf, *hf, *topic, *feat;
    cudaGetSymbolAddress((void**)&qf,    g_qfeat);
    cudaGetSymbolAddress((void**)&hf,    g_hfeat);
    cudaGetSymbolAddress((void**)&topic, g_topic);
    cudaGetSymbolAddress((void**)&feat,  g_feat);

    cudaFuncSetAttribute(gated_gemm, cudaFuncAttributeMaxDynamicSharedMemorySize,
                         GG_SMEM_BYTES);
    const int attn_smem = ATTN_SMEM_FLOATS * (int)sizeof(float);
    cudaFuncSetAttribute(attn_kernel, cudaFuncAttributeMaxDynamicSharedMemorySize,
                         attn_smem);

    // gated transforms (3xBF16 tensor-core GEMMs)
    gated_gemm<<<dim3((BS * SL_Q) / BM, GN / BN), 256, GG_SMEM_BYTES>>>(q_enc, Wq_y, bq_y, Wq_g, bq_g, qf);
    gated_gemm<<<dim3((BS * NUM_R * SL_H) / BM, GN / BN), 256, GG_SMEM_BYTES>>>(h_enc, Wh_y, bh_y, Wh_g, bh_g, hf);

    // per-(b,r) attention + topic
    attn_kernel<<<dim3(NUM_R, BS), 256, attn_smem>>>(qf, hf, h_embed, notpad, cms, topic);

    // concat + reduce over r
    feat_build<<<(BS * SL_Q * FEATD) / 256, 256>>>(q_embed, topic, feat);

    // final gated output
    final_gemm<<<dim3((BS * SL_Q) / FBM, (FEATD + FBN - 1) / FBN), 256>>>(feat, Wg, bg, out);
}

// round 7
// speedup vs baseline: 3.4376x; 2.0492x over previous
#include <cuda_runtime.h>
#include <cuda_bf16.h>
#include <cstdint>

// ---------------------------------------------------------------------------
// Arch dispatch: tcgen05 only when compiling an arch/family-specific target
// ---------------------------------------------------------------------------
#if defined(__CUDA_ARCH_FEAT_SM103_ALL) || defined(__CUDA_ARCH_FEAT_SM100_ALL) || \
    (defined(__CUDA_ARCH_FAMILY_SPECIFIC__) && (__CUDA_ARCH_FAMILY_SPECIFIC__ == 1030 || __CUDA_ARCH_FAMILY_SPECIFIC__ == 1000)) || \
    (defined(__CUDA_ARCH_SPECIFIC__) && (__CUDA_ARCH_SPECIFIC__ == 1030 || __CUDA_ARCH_SPECIFIC__ == 1000))
#define USE_TC 1
#else
#define USE_TC 0
#endif

// ---------------------------------------------------------------------------
// Shapes
// ---------------------------------------------------------------------------
#define BS      32
#define NUM_R   10
#define SL_Q    20
#define SL_H    40
#define WE      300
#define LSTM    1024
#define BILSTM  2048
#define FEATD   600

#define MQ (BS * SL_Q)          // 640
#define MH (BS * NUM_R * SL_H)  // 12800
#define KW (BILSTM / 2)         // 1024 packed kpair words per row

// ---------------------------------------------------------------------------
// Scratch (device globals)
// ---------------------------------------------------------------------------
__device__ float g_qfeat[MQ * LSTM];
__device__ float g_hfeat[MH * LSTM];
__device__ float g_topic[BS * NUM_R * SL_Q * WE];
__device__ float g_feat [MQ * FEATD];

// packed bf16 kpair words
__device__ uint32_t g_xq_h[MQ * KW],  g_xq_l[MQ * KW];
__device__ uint32_t g_xh_h[MH * KW],  g_xh_l[MH * KW];
// weights transposed to [N][K], packed kpairs: [N][KW]
__device__ uint32_t g_wqy_h[LSTM * KW], g_wqy_l[LSTM * KW];
__device__ uint32_t g_wqg_h[LSTM * KW], g_wqg_l[LSTM * KW];
__device__ uint32_t g_why_h[LSTM * KW], g_why_l[LSTM * KW];
__device__ uint32_t g_whg_h[LSTM * KW], g_whg_l[LSTM * KW];

// ---------------------------------------------------------------------------
// Helpers
// ---------------------------------------------------------------------------
__device__ __forceinline__ float leaky(float x) {
    return x >= 0.f ? x : 0.01f * x;
}

__device__ __forceinline__ void split2(float a, float b, uint32_t& hi, uint32_t& lo) {
    __nv_bfloat16 ha = __float2bfloat16(a);
    __nv_bfloat16 hb = __float2bfloat16(b);
    __nv_bfloat16 la = __float2bfloat16(a - __bfloat162float(ha));
    __nv_bfloat16 lb = __float2bfloat16(b - __bfloat162float(hb));
    union { __nv_bfloat162 v; uint32_t u; } ph, pl;
    ph.v.x = ha; ph.v.y = hb; pl.v.x = la; pl.v.y = lb;
    hi = ph.u; lo = pl.u;
}

__device__ __forceinline__ void cpasync16(uint32_t dst, const void* src) {
    asm volatile("cp.async.cg.shared.global [%0], [%1], 16;"
                 :: "r"(dst), "l"(src) : "memory");
}

__device__ __forceinline__ void mma_bf16(float c[4], const uint32_t a[4],
                                         uint32_t b0, uint32_t b1) {
    asm volatile(
        "mma.sync.aligned.m16n8k16.row.col.f32.bf16.bf16.f32 "
        "{%0,%1,%2,%3},{%4,%5,%6,%7},{%8,%9},{%0,%1,%2,%3};"
        : "+f"(c[0]), "+f"(c[1]), "+f"(c[2]), "+f"(c[3])
        : "r"(a[0]), "r"(a[1]), "r"(a[2]), "r"(a[3]), "r"(b0), "r"(b1));
}

#if USE_TC
__device__ __forceinline__ uint32_t elect_one() {
    uint32_t pred;
    asm volatile("{\n\t.reg .pred p;\n\telect.sync _|p, 0xFFFFFFFF;\n\t"
                 "selp.b32 %0, 1, 0, p;\n\t}" : "=r"(pred));
    return pred;
}
__device__ __forceinline__ void mbar_init(uint32_t mbar, uint32_t cnt) {
    asm volatile("mbarrier.init.shared.b64 [%0], %1;" :: "r"(mbar), "r"(cnt) : "memory");
}
__device__ __forceinline__ void mbar_inval(uint32_t mbar) {
    asm volatile("mbarrier.inval.shared.b64 [%0];" :: "r"(mbar) : "memory");
}
__device__ __forceinline__ void mbar_wait(uint32_t mbar, uint32_t parity) {
    asm volatile(
        "{\n\t.reg .pred P;\n\t"
        "WAIT_%=:\n\t"
        "mbarrier.try_wait.parity.acquire.cta.shared::cta.b64 P, [%0], %1, 0x989680;\n\t"
        "@P bra DONE_%=;\n\t"
        "bra WAIT_%=;\n\t"
        "DONE_%=:\n\t}"
        :: "r"(mbar), "r"(parity) : "memory");
}
__device__ __forceinline__ uint64_t sdesc(uint32_t addr) {
    return (2ull << 61) | (1ull << 46) | (64ull << 32) | (1ull << 16)
         | ((uint64_t)(addr >> 4) & 0x3FFF);
}
__device__ __forceinline__ void mma_ss(uint32_t d, uint64_t a, uint64_t b,
                                       uint32_t idesc, uint32_t en) {
    asm volatile(
        "{\n\t.reg .pred p;\n\tsetp.ne.u32 p, %4, 0;\n\t"
        "tcgen05.mma.cta_group::1.kind::f16 [%0], %1, %2, %3, {%5, %5, %5, %5}, p;\n\t}"
        :: "r"(d), "l"(a), "l"(b), "r"(idesc), "r"(en), "r"(0u)
        : "memory");
}
__device__ __forceinline__ void ldtm_x32(uint32_t* r, uint32_t a) {
    asm volatile(
        "tcgen05.ld.sync.aligned.32x32b.x32.b32 "
        "{%0,%1,%2,%3,%4,%5,%6,%7,%8,%9,%10,%11,%12,%13,%14,%15,"
        "%16,%17,%18,%19,%20,%21,%22,%23,%24,%25,%26,%27,%28,%29,%30,%31}, [%32];"
        : "=r"(r[0]),  "=r"(r[1]),  "=r"(r[2]),  "=r"(r[3]),
          "=r"(r[4]),  "=r"(r[5]),  "=r"(r[6]),  "=r"(r[7]),
          "=r"(r[8]),  "=r"(r[9]),  "=r"(r[10]), "=r"(r[11]),
          "=r"(r[12]), "=r"(r[13]), "=r"(r[14]), "=r"(r[15]),
          "=r"(r[16]), "=r"(r[17]), "=r"(r[18]), "=r"(r[19]),
          "=r"(r[20]), "=r"(r[21]), "=r"(r[22]), "=r"(r[23]),
          "=r"(r[24]), "=r"(r[25]), "=r"(r[26]), "=r"(r[27]),
          "=r"(r[28]), "=r"(r[29]), "=r"(r[30]), "=r"(r[31])
        : "r"(a));
}
#endif  // USE_TC

// ---------------------------------------------------------------------------
// Precompute: X -> packed kpair bf16 hi/lo words
// ---------------------------------------------------------------------------
__global__ __launch_bounds__(256)
void split_x_pack(const float* __restrict__ x, uint32_t* __restrict__ hi,
                  uint32_t* __restrict__ lo, int n4) {
    int i = blockIdx.x * 256 + threadIdx.x;
    if (i >= n4) return;
    float4 v = ((const float4*)x)[i];
    uint32_t h0, l0, h1, l1;
    split2(v.x, v.y, h0, l0);
    split2(v.z, v.w, h1, l1);
    ((uint2*)hi)[i] = make_uint2(h0, h1);
    ((uint2*)lo)[i] = make_uint2(l0, l1);
}

// ---------------------------------------------------------------------------
// Precompute: W [2048,1024] -> transposed packed [1024][KW] hi/lo words
// ---------------------------------------------------------------------------
__global__ __launch_bounds__(256)
void split_wt_pack(const float* __restrict__ W, uint32_t* __restrict__ thi,
                   uint32_t* __restrict__ tlo) {
    __shared__ float t[32][33];
    int k0 = blockIdx.x * 32, n0 = blockIdx.y * 32;
    int tx = threadIdx.x & 31, ty = threadIdx.x >> 5;
#pragma unroll
    for (int j = 0; j < 4; j++)
        t[ty + 8 * j][tx] = W[(size_t)(k0 + ty + 8 * j) * LSTM + n0 + tx];
    __syncthreads();
#pragma unroll
    for (int w = threadIdx.x; w < 512; w += 256) {
        int nn = w >> 4;      // 0..31
        int kp = w & 15;      // 0..15
        uint32_t h, l;
        split2(t[2 * kp][nn], t[2 * kp + 1][nn], h, l);
        size_t o = (size_t)(n0 + nn) * KW + (k0 >> 1) + kp;
        thi[o] = h;
        tlo[o] = l;
    }
}

// ---------------------------------------------------------------------------
// Gated transform: out = tanh(X@Wy + by) * leaky_relu(X@Wg + bg)
// 3xBF16 split. Tile 128x128, K-chunk 64, grid (n-tiles=8 FAST, m-tiles).
// smem per stage: 6 regions x 16KB (Ah, Al, Byh, Byl, Bgh, Bgl), SW128 rows.
// Path A (sm_103a): tcgen05 SS MMA, TMEM accum.  Path B: legacy mma.m16n8k16.
// ---------------------------------------------------------------------------
#define TBM 128
#define TBN 128
#define TKC 64
#define NCHUNK (BILSTM / TKC)          // 32
#define CH_BYTES 98304
#define SM_CTRL 1024
#define GG_SMEM (SM_CTRL + 2 * CH_BYTES)
#define IDESC_GG 0x8200490u

__global__ __launch_bounds__(256, 1)
void gated_gemm_u(const uint32_t* __restrict__ Xh, const uint32_t* __restrict__ Xl,
                  const uint32_t* __restrict__ Wyh, const uint32_t* __restrict__ Wyl,
                  const uint32_t* __restrict__ Wgh, const uint32_t* __restrict__ Wgl,
                  const float* __restrict__ by, const float* __restrict__ bg,
                  float* __restrict__ out) {
    extern __shared__ char smem[];
    const uint32_t smem_base = (uint32_t)__cvta_generic_to_shared(smem);
    const int tid  = threadIdx.x;
    const int warp = tid >> 5;
    const int lane = tid & 31;
    const int n0 = blockIdx.x * TBN;   // n fastest -> L2 A reuse
    const int m0 = blockIdx.y * TBM;

    // common cp.async loader: one chunk = 6 regions x (128 rows x 128B), SW128
    auto load_chunk = [&](int c) {
        const uint32_t bb = smem_base + SM_CTRL + (uint32_t)(c & 1) * CH_BYTES;
        const int kw0 = c * (TKC / 2);
#pragma unroll
        for (int i = 0; i < 24; i++) {
            const int reg = i >> 2;
            const int v   = tid + (i & 3) * 256;
            const int row = v >> 3, seg = v & 7;
            const uint32_t* s; int rb; uint32_t doff;
            if      (reg == 0) { s = Xh;  rb = m0; doff = 0; }
            else if (reg == 1) { s = Xl;  rb = m0; doff = 16384; }
            else if (reg == 2) { s = Wyh; rb = n0; doff = 32768; }
            else if (reg == 3) { s = Wyl; rb = n0; doff = 49152; }
            else if (reg == 4) { s = Wgh; rb = n0; doff = 65536; }
            else               { s = Wgl; rb = n0; doff = 81920; }
            const void* src = s + (size_t)(rb + row) * KW + kw0 + seg * 4;
            uint32_t bo = (uint32_t)(row * 128 + seg * 16);
            cpasync16(bb + doff + (bo ^ ((bo >> 3) & 0x70)), src);
        }
        asm volatile("cp.async.commit_group;" ::: "memory");
    };

#if USE_TC
    // ---------------- tcgen05 path ----------------
    const uint32_t mb0 = smem_base + 16, mb1 = smem_base + 24;
    if (warp == 0)
        asm volatile("tcgen05.alloc.cta_group::1.sync.aligned.shared::cta.b32 [%0], %1;"
                     :: "r"(smem_base), "r"(256u) : "memory");
    if (tid == 0) { mbar_init(mb0, 1); mbar_init(mb1, 1); }
    __syncthreads();
    uint32_t tmem;
    asm volatile("ld.shared.b32 %0, [%1];" : "=r"(tmem) : "r"(smem_base));
    const uint32_t tY = tmem, tG = tmem + 128;

    int ph0 = 0, ph1 = 0;
    for (int c = 0; c < NCHUNK; c++) {
        const int buf = c & 1;
        if (c >= 2) {
            if (buf) { mbar_wait(mb1, (uint32_t)ph1); ph1 ^= 1; }
            else     { mbar_wait(mb0, (uint32_t)ph0); ph0 ^= 1; }
        }
        load_chunk(c);
        asm volatile("cp.async.wait_group 0;" ::: "memory");
        asm volatile("tcgen05.fence::before_thread_sync;" ::: "memory");
        asm volatile("fence.proxy.async.shared::cta;" ::: "memory");
        __syncthreads();

        if (warp == 0) {
            asm volatile("tcgen05.fence::after_thread_sync;" ::: "memory");
            if (elect_one()) {
                const uint32_t bb = smem_base + SM_CTRL + (uint32_t)buf * CH_BYTES;
                uint64_t dAh = sdesc(bb),         dAl = sdesc(bb + 16384);
                uint64_t dYh = sdesc(bb + 32768), dYl = sdesc(bb + 49152);
                uint64_t dGh = sdesc(bb + 65536), dGl = sdesc(bb + 81920);
#pragma unroll
                for (int s = 0; s < 4; s++) {
                    uint64_t o = (uint64_t)(s * 2);
                    uint32_t en0 = (c == 0 && s == 0) ? 0u : 1u;
                    mma_ss(tY, dAh + o, dYh + o, IDESC_GG, en0);
                    mma_ss(tY, dAh + o, dYl + o, IDESC_GG, 1u);
                    mma_ss(tY, dAl + o, dYh + o, IDESC_GG, 1u);
                    mma_ss(tG, dAh + o, dGh + o, IDESC_GG, en0);
                    mma_ss(tG, dAh + o, dGl + o, IDESC_GG, 1u);
                    mma_ss(tG, dAl + o, dGh + o, IDESC_GG, 1u);
                }
                asm volatile(
                    "tcgen05.commit.cta_group::1.mbarrier::arrive::one.shared::cluster.b64 [%0];"
                    :: "r"(buf ? mb1 : mb0) : "memory");
            }
        }
    }
    mbar_wait(mb1, (uint32_t)ph1);
    asm volatile("tcgen05.fence::after_thread_sync;" ::: "memory");

    float* ep = (float*)(smem + SM_CTRL);   // 128 x 129
    if (warp < 4) {
        const int m = warp * 32 + lane;
#pragma unroll
        for (int s = 0; s < 4; s++) {
            uint32_t ry[32], rg[32];
            ldtm_x32(ry, tY + s * 32);
            ldtm_x32(rg, tG + s * 32);
            asm volatile("tcgen05.wait::ld.sync.aligned;" ::: "memory");
#pragma unroll
            for (int cc = 0; cc < 32; cc++) {
                int n = n0 + s * 32 + cc;
                float yv = __uint_as_float(ry[cc]) + by[n];
                float gv = __uint_as_float(rg[cc]) + bg[n];
                ep[m * 129 + s * 32 + cc] = tanhf(yv) * leaky(gv);
            }
        }
    }
    __syncthreads();
    for (int i = tid; i < TBM * TBN; i += 256) {
        int row = i >> 7, col = i & 127;
        out[(size_t)(m0 + row) * LSTM + n0 + col] = ep[row * 129 + col];
    }
    __syncthreads();
    if (tid == 0) { mbar_inval(mb0); mbar_inval(mb1); }
    __syncthreads();
    if (warp == 0) {
        asm volatile("tcgen05.relinquish_alloc_permit.cta_group::1.sync.aligned;");
        asm volatile("tcgen05.dealloc.cta_group::1.sync.aligned.b32 %0, %1;"
                     :: "r"(tmem), "r"(256u));
    }
#else
    // ---------------- legacy mma.m16n8k16 fallback ----------------
    // 8 warps: 2m x 4n; warp tile 64x32 (mt=4 of m16, nt=4 of n8)
    const int wm = (warp >> 2) * 64;
    const int wn = (warp & 3) * 32;
    const int ar = lane >> 2;
    const int ac = lane & 3;

    float accY[4][4][4] = {};
    float accG[4][4][4] = {};

    load_chunk(0);
    for (int c = 0; c < NCHUNK; c++) {
        if (c + 1 < NCHUNK) {
            load_chunk(c + 1);
            asm volatile("cp.async.wait_group 1;" ::: "memory");
        } else {
            asm volatile("cp.async.wait_group 0;" ::: "memory");
        }
        __syncthreads();
        const char* bb = smem + SM_CTRL + (size_t)(c & 1) * CH_BYTES;
        // swizzled word load: region byte offset, row, kword index
        auto lw = [&](uint32_t roff, int row, int kw) -> uint32_t {
            uint32_t off = (uint32_t)(row * 128) + (((uint32_t)kw * 4) ^ ((uint32_t)(row & 7) << 4));
            return *(const uint32_t*)(bb + roff + off);
        };
#pragma unroll
        for (int ks = 0; ks < 4; ks++) {
            const int kpb = ks * 8;
            uint32_t ah[4][4], al[4][4];
#pragma unroll
            for (int mt = 0; mt < 4; mt++) {
                int r0 = wm + 16 * mt + ar;
                ah[mt][0] = lw(0, r0,     kpb + ac);
                ah[mt][1] = lw(0, r0 + 8, kpb + ac);
                ah[mt][2] = lw(0, r0,     kpb + ac + 4);
                ah[mt][3] = lw(0, r0 + 8, kpb + ac + 4);
                al[mt][0] = lw(16384, r0,     kpb + ac);
                al[mt][1] = lw(16384, r0 + 8, kpb + ac);
                al[mt][2] = lw(16384, r0,     kpb + ac + 4);
                al[mt][3] = lw(16384, r0 + 8, kpb + ac + 4);
            }
#pragma unroll
            for (int nt = 0; nt < 4; nt++) {
                int n = wn + 8 * nt + (lane >> 2);
                uint32_t byh0 = lw(32768, n, kpb + ac);
                uint32_t byh1 = lw(32768, n, kpb + ac + 4);
                uint32_t byl0 = lw(49152, n, kpb + ac);
                uint32_t byl1 = lw(49152, n, kpb + ac + 4);
                uint32_t bgh0 = lw(65536, n, kpb + ac);
                uint32_t bgh1 = lw(65536, n, kpb + ac + 4);
                uint32_t bgl0 = lw(81920, n, kpb + ac);
                uint32_t bgl1 = lw(81920, n, kpb + ac + 4);
#pragma unroll
                for (int mt = 0; mt < 4; mt++) {
                    mma_bf16(accY[mt][nt], al[mt], byh0, byh1);
                    mma_bf16(accY[mt][nt], ah[mt], byl0, byl1);
                    mma_bf16(accY[mt][nt], ah[mt], byh0, byh1);
                    mma_bf16(accG[mt][nt], al[mt], bgh0, bgh1);
                    mma_bf16(accG[mt][nt], ah[mt], bgl0, bgl1);
                    mma_bf16(accG[mt][nt], ah[mt], bgh0, bgh1);
                }
            }
        }
        __syncthreads();
    }

#pragma unroll
    for (int mt = 0; mt < 4; mt++) {
#pragma unroll
        for (int nt = 0; nt < 4; nt++) {
            int gr = m0 + wm + 16 * mt + ar;
            int gc = n0 + wn + 8 * nt + 2 * ac;
            float b_y0 = by[gc], b_y1 = by[gc + 1];
            float b_g0 = bg[gc], b_g1 = bg[gc + 1];
            float v00 = tanhf(accY[mt][nt][0] + b_y0) * leaky(accG[mt][nt][0] + b_g0);
            float v01 = tanhf(accY[mt][nt][1] + b_y1) * leaky(accG[mt][nt][1] + b_g1);
            float v10 = tanhf(accY[mt][nt][2] + b_y0) * leaky(accG[mt][nt][2] + b_g0);
            float v11 = tanhf(accY[mt][nt][3] + b_y1) * leaky(accG[mt][nt][3] + b_g1);
            *(float2*)&out[(size_t)gr * LSTM + gc]       = make_float2(v00, v01);
            *(float2*)&out[(size_t)(gr + 8) * LSTM + gc] = make_float2(v10, v11);
        }
    }
#endif
}

// ---------------------------------------------------------------------------
// Kernel 2: per-(b,r) attention block (proven)
// ---------------------------------------------------------------------------
#define CK 64
#define QS_STRIDE 65
#define HS_STRIDE 65
#define ATTN_SMEM_FLOATS (12000 + SL_Q * QS_STRIDE + SL_H * HS_STRIDE + SL_Q * SL_H)

__global__ __launch_bounds__(256)
void attn_kernel(const float* __restrict__ qf, const float* __restrict__ hf,
                 const float* __restrict__ emb, const float* __restrict__ notpad,
                 const float* __restrict__ cms, float* __restrict__ topic) {
    extern __shared__ float sm[];
    float* emb_s = sm;
    float* qs = emb_s + 12000;
    float* hs = qs + SL_Q * QS_STRIDE;
    float* S  = hs + SL_H * HS_STRIDE;

    const int t = threadIdx.x;
    const int r = blockIdx.x;
    const int b = blockIdx.y;
    const int br = b * NUM_R + r;

    for (int i = t; i < SL_H * WE; i += 256)
        emb_s[i] = emb[(size_t)br * (SL_H * WE) + i];

    const int q2 = t / 20;
    const int h2 = t % 20;
    float acc00 = 0.f, acc01 = 0.f, acc10 = 0.f, acc11 = 0.f;

    for (int kc = 0; kc < LSTM; kc += CK) {
        for (int i = t; i < SL_Q * CK; i += 256) {
            int row = i >> 6, col = i & 63;
            qs[row * QS_STRIDE + col] = qf[(size_t)(b * SL_Q + row) * LSTM + kc + col];
        }
        for (int i = t; i < SL_H * CK; i += 256) {
            int row = i >> 6, col = i & 63;
            hs[row * HS_STRIDE + col] = hf[(size_t)(br * SL_H + row) * LSTM + kc + col];
        }
        __syncthreads();
        if (t < 200) {
            const float* q0p = &qs[(2 * q2)     * QS_STRIDE];
            const float* q1p = &qs[(2 * q2 + 1) * QS_STRIDE];
            const float* h0p = &hs[(2 * h2)     * HS_STRIDE];
            const float* h1p = &hs[(2 * h2 + 1) * HS_STRIDE];
#pragma unroll 8
            for (int k = 0; k < CK; k++) {
                float q0 = q0p[k], q1 = q1p[k];
                float h0 = h0p[k], h1 = h1p[k];
                acc00 += q0 * h0; acc01 += q0 * h1;
                acc10 += q1 * h0; acc11 += q1 * h1;
            }
        }
        __syncthreads();
    }

    if (t < 200) {
        S[(2 * q2)     * SL_H + 2 * h2]     = acc00;
        S[(2 * q2)     * SL_H + 2 * h2 + 1] = acc01;
        S[(2 * q2 + 1) * SL_H + 2 * h2]     = acc10;
        S[(2 * q2 + 1) * SL_H + 2 * h2 + 1] = acc11;
    }
    __syncthreads();

    if (t < SL_Q) {
        float mx = -1e30f;
        for (int h = 0; h < SL_H; h++) {
            float m = notpad[(size_t)br * SL_H + h];
            float s = S[t * SL_H + h] * m + (m - 1.0f) * 10000.0f;
            S[t * SL_H + h] = s;
            mx = fmaxf(mx, s);
        }
        float den = 0.f;
        for (int h = 0; h < SL_H; h++) {
            float e = expf(S[t * SL_H + h] - mx);
            S[t * SL_H + h] = e;
            den += e;
        }
        float inv = 1.0f / den;
        for (int h = 0; h < SL_H; h++) S[t * SL_H + h] *= inv;
    }
    __syncthreads();

    const float c = cms[br];
    for (int o = t; o < SL_Q * WE; o += 256) {
        int q = o / WE, e = o % WE;
        float s = 0.f;
#pragma unroll 8
        for (int h = 0; h < SL_H; h++)
            s += S[q * SL_H + h] * emb_s[h * WE + e];
        topic[(size_t)(br * SL_Q + q) * WE + e] = s * c;
    }
}

// ---------------------------------------------------------------------------
// Kernel 3: feat = concat(q_embed, sum_r topic)
// ---------------------------------------------------------------------------
__global__ __launch_bounds__(256)
void feat_build(const float* __restrict__ q_embed, const float* __restrict__ topic,
                float* __restrict__ feat) {
    int idx = blockIdx.x * 256 + threadIdx.x;
    int m  = idx / FEATD;
    int e2 = idx % FEATD;
    float v;
    if (e2 < WE) {
        v = q_embed[(size_t)m * WE + e2];
    } else {
        int e = e2 - WE;
        int b = m / SL_Q, q = m % SL_Q;
        v = 0.f;
#pragma unroll
        for (int r = 0; r < NUM_R; r++)
            v += topic[(size_t)((b * NUM_R + r) * SL_Q + q) * WE + e];
    }
    feat[idx] = v;
}

// ---------------------------------------------------------------------------
// Kernel 4: out = sigmoid(feat@Wg + bg) * feat
// ---------------------------------------------------------------------------
#define FBM 64
#define FBN 64
#define FBK 16

__global__ __launch_bounds__(256)
void final_gemm(const float* __restrict__ feat, const float* __restrict__ Wg,
                const float* __restrict__ bg, float* __restrict__ out) {
    __shared__ float Fs[FBM][FBK + 1];
    __shared__ float Bsm[FBK][FBN + 1];

    const int t = threadIdx.x;
    const int ty = t >> 4, tx = t & 15;
    const int m0 = blockIdx.x * FBM;
    const int n0 = blockIdx.y * FBN;

    float acc[4][4];
#pragma unroll
    for (int i = 0; i < 4; i++)
#pragma unroll
        for (int j = 0; j < 4; j++) acc[i][j] = 0.f;

    for (int k0 = 0; k0 < FEATD; k0 += FBK) {
        for (int i = t; i < FBM * FBK; i += 256) {
            int r = i >> 4, c = i & 15;
            int k = k0 + c;
            Fs[r][c] = (k < FEATD) ? feat[(size_t)(m0 + r) * FEATD + k] : 0.f;
        }
        for (int i = t; i < FBK * FBN; i += 256) {
            int r = i >> 6, c = i & 63;
            int k = k0 + r, n = n0 + c;
            Bsm[r][c] = (k < FEATD && n < FEATD) ? Wg[(size_t)k * FEATD + n] : 0.f;
        }
        __syncthreads();
#pragma unroll
        for (int k = 0; k < FBK; k++) {
            float a[4], bb[4];
#pragma unroll
            for (int i = 0; i < 4; i++) a[i]  = Fs[ty * 4 + i][k];
#pragma unroll
            for (int j = 0; j < 4; j++) bb[j] = Bsm[k][tx * 4 + j];
#pragma unroll
            for (int i = 0; i < 4; i++)
#pragma unroll
                for (int j = 0; j < 4; j++) acc[i][j] += a[i] * bb[j];
        }
        __syncthreads();
    }

#pragma unroll
    for (int i = 0; i < 4; i++) {
        int row = m0 + ty * 4 + i;
#pragma unroll
        for (int j = 0; j < 4; j++) {
            int col = n0 + tx * 4 + j;
            if (col < FEATD) {
                float v = acc[i][j] + bg[col];
                float g = 1.0f / (1.0f + expf(-v));
                out[(size_t)row * FEATD + col] = g * feat[(size_t)row * FEATD + col];
            }
        }
    }
}

// ---------------------------------------------------------------------------
// Host launcher
// ---------------------------------------------------------------------------
extern "C" void kernel_launch(void* const* d_in, const int* in_sizes, int n_in,
                              void* d_out, int out_size) {
    const float* q_embed = (const float*)d_in[0];
    const float* q_enc   = (const float*)d_in[1];
    const float* h_embed = (const float*)d_in[2];
    const float* h_enc   = (const float*)d_in[3];
    const float* notpad  = (const float*)d_in[4];
    const float* cms     = (const float*)d_in[5];
    const float* Wq_y = (const float*)d_in[6];
    const float* bq_y = (const float*)d_in[7];
    const float* Wq_g = (const float*)d_in[8];
    const float* bq_g = (const float*)d_in[9];
    const float* Wh_y = (const float*)d_in[10];
    const float* bh_y = (const float*)d_in[11];
    const float* Wh_g = (const float*)d_in[12];
    const float* bh_g = (const float*)d_in[13];
    const float* Wg   = (const float*)d_in[14];
    const float* bg   = (const float*)d_in[15];
    float* out = (float*)d_out;

    float *qf, *hf, *topic, *feat;
    cudaGetSymbolAddress((void**)&qf,    g_qfeat);
    cudaGetSymbolAddress((void**)&hf,    g_hfeat);
    cudaGetSymbolAddress((void**)&topic, g_topic);
    cudaGetSymbolAddress((void**)&feat,  g_feat);

    uint32_t *xq_h, *xq_l, *xh_h, *xh_l;
    uint32_t *wqy_h, *wqy_l, *wqg_h, *wqg_l, *why_h, *why_l, *whg_h, *whg_l;
    cudaGetSymbolAddress((void**)&xq_h, g_xq_h);
    cudaGetSymbolAddress((void**)&xq_l, g_xq_l);
    cudaGetSymbolAddress((void**)&xh_h, g_xh_h);
    cudaGetSymbolAddress((void**)&xh_l, g_xh_l);
    cudaGetSymbolAddress((void**)&wqy_h, g_wqy_h);
    cudaGetSymbolAddress((void**)&wqy_l, g_wqy_l);
    cudaGetSymbolAddress((void**)&wqg_h, g_wqg_h);
    cudaGetSymbolAddress((void**)&wqg_l, g_wqg_l);
    cudaGetSymbolAddress((void**)&why_h, g_why_h);
    cudaGetSymbolAddress((void**)&why_l, g_why_l);
    cudaGetSymbolAddress((void**)&whg_h, g_whg_h);
    cudaGetSymbolAddress((void**)&whg_l, g_whg_l);

    cudaFuncSetAttribute(gated_gemm_u, cudaFuncAttributeMaxDynamicSharedMemorySize,
                         GG_SMEM);
    const int attn_smem = ATTN_SMEM_FLOATS * (int)sizeof(float);
    cudaFuncSetAttribute(attn_kernel, cudaFuncAttributeMaxDynamicSharedMemorySize,
                         attn_smem);

    // --- precompute packed bf16 splits ---
    {
        int n4q = MQ * BILSTM / 4;
        split_x_pack<<<(n4q + 255) / 256, 256>>>(q_enc, xq_h, xq_l, n4q);
        int n4h = MH * BILSTM / 4;
        split_x_pack<<<(n4h + 255) / 256, 256>>>(h_enc, xh_h, xh_l, n4h);
        dim3 wg(BILSTM / 32, LSTM / 32);
        split_wt_pack<<<wg, 256>>>(Wq_y, wqy_h, wqy_l);
        split_wt_pack<<<wg, 256>>>(Wq_g, wqg_h, wqg_l);
        split_wt_pack<<<wg, 256>>>(Wh_y, why_h, why_l);
        split_wt_pack<<<wg, 256>>>(Wh_g, whg_h, whg_l);
    }

    // --- gated transforms (arch-dispatched kernel; n-tiles fastest) ---
    gated_gemm_u<<<dim3(LSTM / TBN, MQ / TBM), 256, GG_SMEM>>>(
        xq_h, xq_l, wqy_h, wqy_l, wqg_h, wqg_l, bq_y, bq_g, qf);
    gated_gemm_u<<<dim3(LSTM / TBN, MH / TBM), 256, GG_SMEM>>>(
        xh_h, xh_l, why_h, why_l, whg_h, whg_l, bh_y, bh_g, hf);

    // --- attention + topic ---
    attn_kernel<<<dim3(NUM_R, BS), 256, attn_smem>>>(qf, hf, h_embed, notpad, cms, topic);

    // --- concat + reduce over r ---
    feat_build<<<(MQ * FEATD) / 256, 256>>>(q_embed, topic, feat);

    // --- final gated output ---
    final_gemm<<<dim3(MQ / FBM, (FEATD + FBN - 1) / FBN), 256>>>(feat, Wg, bg, out);
}

// round 8
// speedup vs baseline: 3.6233x; 1.0540x over previous
#include <cuda_runtime.h>
#include <cuda_bf16.h>
#include <cstdint>

// ---------------------------------------------------------------------------
// Arch dispatch: tcgen05 only when compiling an arch/family-specific target
// ---------------------------------------------------------------------------
#if defined(__CUDA_ARCH_FEAT_SM103_ALL) || defined(__CUDA_ARCH_FEAT_SM100_ALL) || \
    (defined(__CUDA_ARCH_FAMILY_SPECIFIC__) && (__CUDA_ARCH_FAMILY_SPECIFIC__ == 1030 || __CUDA_ARCH_FAMILY_SPECIFIC__ == 1000)) || \
    (defined(__CUDA_ARCH_SPECIFIC__) && (__CUDA_ARCH_SPECIFIC__ == 1030 || __CUDA_ARCH_SPECIFIC__ == 1000))
#define USE_TC 1
#else
#define USE_TC 0
#endif

// ---------------------------------------------------------------------------
// Shapes
// ---------------------------------------------------------------------------
#define BS      32
#define NUM_R   10
#define SL_Q    20
#define SL_H    40
#define WE      300
#define LSTM    1024
#define BILSTM  2048
#define FEATD   600

#define MQ (BS * SL_Q)          // 640
#define MH (BS * NUM_R * SL_H)  // 12800
#define KW (BILSTM / 2)         // 1024 packed kpair words per row

// ---------------------------------------------------------------------------
// Scratch (device globals)
// ---------------------------------------------------------------------------
__device__ float g_qfeat[MQ * LSTM];
__device__ float g_hfeat[MH * LSTM];
__device__ float g_topic[BS * NUM_R * SL_Q * WE];
__device__ float g_feat [MQ * FEATD];

__device__ uint32_t g_xq_h[MQ * KW],  g_xq_l[MQ * KW];
__device__ uint32_t g_xh_h[MH * KW],  g_xh_l[MH * KW];
__device__ uint32_t g_wqy_h[LSTM * KW], g_wqy_l[LSTM * KW];
__device__ uint32_t g_wqg_h[LSTM * KW], g_wqg_l[LSTM * KW];
__device__ uint32_t g_why_h[LSTM * KW], g_why_l[LSTM * KW];
__device__ uint32_t g_whg_h[LSTM * KW], g_whg_l[LSTM * KW];

// ---------------------------------------------------------------------------
// Helpers
// ---------------------------------------------------------------------------
__device__ __forceinline__ float leaky(float x) {
    return x >= 0.f ? x : 0.01f * x;
}

__device__ __forceinline__ void split2(float a, float b, uint32_t& hi, uint32_t& lo) {
    __nv_bfloat16 ha = __float2bfloat16(a);
    __nv_bfloat16 hb = __float2bfloat16(b);
    __nv_bfloat16 la = __float2bfloat16(a - __bfloat162float(ha));
    __nv_bfloat16 lb = __float2bfloat16(b - __bfloat162float(hb));
    union { __nv_bfloat162 v; uint32_t u; } ph, pl;
    ph.v.x = ha; ph.v.y = hb; pl.v.x = la; pl.v.y = lb;
    hi = ph.u; lo = pl.u;
}

__device__ __forceinline__ void cpasync16(uint32_t dst, const void* src) {
    asm volatile("cp.async.cg.shared.global [%0], [%1], 16;"
                 :: "r"(dst), "l"(src) : "memory");
}

__device__ __forceinline__ void mma_bf16(float c[4], const uint32_t a[4],
                                         uint32_t b0, uint32_t b1) {
    asm volatile(
        "mma.sync.aligned.m16n8k16.row.col.f32.bf16.bf16.f32 "
        "{%0,%1,%2,%3},{%4,%5,%6,%7},{%8,%9},{%0,%1,%2,%3};"
        : "+f"(c[0]), "+f"(c[1]), "+f"(c[2]), "+f"(c[3])
        : "r"(a[0]), "r"(a[1]), "r"(a[2]), "r"(a[3]), "r"(b0), "r"(b1));
}

__device__ __forceinline__ void ldsm_x4(uint32_t& r0, uint32_t& r1,
                                        uint32_t& r2, uint32_t& r3, uint32_t addr) {
    asm volatile("ldmatrix.sync.aligned.m8n8.x4.shared.b16 {%0,%1,%2,%3}, [%4];"
                 : "=r"(r0), "=r"(r1), "=r"(r2), "=r"(r3) : "r"(addr));
}

#if USE_TC
__device__ __forceinline__ uint32_t elect_one() {
    uint32_t pred;
    asm volatile("{\n\t.reg .pred p;\n\telect.sync _|p, 0xFFFFFFFF;\n\t"
                 "selp.b32 %0, 1, 0, p;\n\t}" : "=r"(pred));
    return pred;
}
__device__ __forceinline__ void mbar_init(uint32_t mbar, uint32_t cnt) {
    asm volatile("mbarrier.init.shared.b64 [%0], %1;" :: "r"(mbar), "r"(cnt) : "memory");
}
__device__ __forceinline__ void mbar_inval(uint32_t mbar) {
    asm volatile("mbarrier.inval.shared.b64 [%0];" :: "r"(mbar) : "memory");
}
__device__ __forceinline__ void mbar_wait(uint32_t mbar, uint32_t parity) {
    asm volatile(
        "{\n\t.reg .pred P;\n\t"
        "WAIT_%=:\n\t"
        "mbarrier.try_wait.parity.acquire.cta.shared::cta.b64 P, [%0], %1, 0x989680;\n\t"
        "@P bra DONE_%=;\n\t"
        "bra WAIT_%=;\n\t"
        "DONE_%=:\n\t}"
        :: "r"(mbar), "r"(parity) : "memory");
}
__device__ __forceinline__ uint64_t sdesc(uint32_t addr) {
    return (2ull << 61) | (1ull << 46) | (64ull << 32) | (1ull << 16)
         | ((uint64_t)(addr >> 4) & 0x3FFF);
}
__device__ __forceinline__ void mma_ss(uint32_t d, uint64_t a, uint64_t b,
                                       uint32_t idesc, uint32_t en) {
    asm volatile(
        "{\n\t.reg .pred p;\n\tsetp.ne.u32 p, %4, 0;\n\t"
        "tcgen05.mma.cta_group::1.kind::f16 [%0], %1, %2, %3, {%5, %5, %5, %5}, p;\n\t}"
        :: "r"(d), "l"(a), "l"(b), "r"(idesc), "r"(en), "r"(0u)
        : "memory");
}
__device__ __forceinline__ void ldtm_x32(uint32_t* r, uint32_t a) {
    asm volatile(
        "tcgen05.ld.sync.aligned.32x32b.x32.b32 "
        "{%0,%1,%2,%3,%4,%5,%6,%7,%8,%9,%10,%11,%12,%13,%14,%15,"
        "%16,%17,%18,%19,%20,%21,%22,%23,%24,%25,%26,%27,%28,%29,%30,%31}, [%32];"
        : "=r"(r[0]),  "=r"(r[1]),  "=r"(r[2]),  "=r"(r[3]),
          "=r"(r[4]),  "=r"(r[5]),  "=r"(r[6]),  "=r"(r[7]),
          "=r"(r[8]),  "=r"(r[9]),  "=r"(r[10]), "=r"(r[11]),
          "=r"(r[12]), "=r"(r[13]), "=r"(r[14]), "=r"(r[15]),
          "=r"(r[16]), "=r"(r[17]), "=r"(r[18]), "=r"(r[19]),
          "=r"(r[20]), "=r"(r[21]), "=r"(r[22]), "=r"(r[23]),
          "=r"(r[24]), "=r"(r[25]), "=r"(r[26]), "=r"(r[27]),
          "=r"(r[28]), "=r"(r[29]), "=r"(r[30]), "=r"(r[31])
        : "r"(a));
}
#endif  // USE_TC

// ---------------------------------------------------------------------------
// nop kernel (launch-index padding so ncu -s 5 lands on the gemm)
// ---------------------------------------------------------------------------
__global__ void nop_kernel() {}

// ---------------------------------------------------------------------------
// Precompute (fused): X_q and X_h -> packed kpair bf16 hi/lo words
// ---------------------------------------------------------------------------
__global__ __launch_bounds__(256)
void split_x_all(const float* __restrict__ xq, uint32_t* __restrict__ qhi,
                 uint32_t* __restrict__ qlo,
                 const float* __restrict__ xh, uint32_t* __restrict__ hhi,
                 uint32_t* __restrict__ hlo) {
    const int n4q = MQ * BILSTM / 4;
    const int n4h = MH * BILSTM / 4;
    int i = blockIdx.x * 256 + threadIdx.x;
    const float* x; uint32_t *hi, *lo; int j;
    if (i < n4q) { x = xq; hi = qhi; lo = qlo; j = i; }
    else if (i < n4q + n4h) { x = xh; hi = hhi; lo = hlo; j = i - n4q; }
    else return;
    float4 v = ((const float4*)x)[j];
    uint32_t h0, l0, h1, l1;
    split2(v.x, v.y, h0, l0);
    split2(v.z, v.w, h1, l1);
    ((uint2*)hi)[j] = make_uint2(h0, h1);
    ((uint2*)lo)[j] = make_uint2(l0, l1);
}

// ---------------------------------------------------------------------------
// Precompute (fused): 4 weight matrices -> transposed packed [1024][KW] hi/lo
// ---------------------------------------------------------------------------
__global__ __launch_bounds__(256)
void split_wt_all(const float* __restrict__ W0, uint32_t* __restrict__ h0p, uint32_t* __restrict__ l0p,
                  const float* __restrict__ W1, uint32_t* __restrict__ h1p, uint32_t* __restrict__ l1p,
                  const float* __restrict__ W2, uint32_t* __restrict__ h2p, uint32_t* __restrict__ l2p,
                  const float* __restrict__ W3, uint32_t* __restrict__ h3p, uint32_t* __restrict__ l3p) {
    const float* W; uint32_t *thi, *tlo;
    switch (blockIdx.z) {
        case 0:  W = W0; thi = h0p; tlo = l0p; break;
        case 1:  W = W1; thi = h1p; tlo = l1p; break;
        case 2:  W = W2; thi = h2p; tlo = l2p; break;
        default: W = W3; thi = h3p; tlo = l3p; break;
    }
    __shared__ float t[32][33];
    int k0 = blockIdx.x * 32, n0 = blockIdx.y * 32;
    int tx = threadIdx.x & 31, ty = threadIdx.x >> 5;
#pragma unroll
    for (int j = 0; j < 4; j++)
        t[ty + 8 * j][tx] = W[(size_t)(k0 + ty + 8 * j) * LSTM + n0 + tx];
    __syncthreads();
    for (int w = threadIdx.x; w < 512; w += 256) {
        int nn = w >> 4;
        int kp = w & 15;
        uint32_t h, l;
        split2(t[2 * kp][nn], t[2 * kp + 1][nn], h, l);
        size_t o = (size_t)(n0 + nn) * KW + (k0 >> 1) + kp;
        thi[o] = h;
        tlo[o] = l;
    }
}

// ---------------------------------------------------------------------------
// Gated transform: out = tanh(X@Wy + by) * leaky_relu(X@Wg + bg), 3xBF16
// Merged q+h launch: grid (8 n-tiles FAST, 105 m-tiles: 0-4=q, 5-104=h).
// Tile 128x128, K-chunk 64, cp.async double-buffered, ldmatrix fragment loads.
// ---------------------------------------------------------------------------
#define TBM 128
#define TBN 128
#define TKC 64
#define NCHUNK (BILSTM / TKC)          // 32
#define CH_BYTES 98304
#define SM_CTRL 1024
#define GG_SMEM (SM_CTRL + 2 * CH_BYTES)
#define IDESC_GG 0x8200490u

__global__ __launch_bounds__(256, 1)
void gated_gemm_all(const uint32_t* __restrict__ qXh, const uint32_t* __restrict__ qXl,
                    const uint32_t* __restrict__ qWyh, const uint32_t* __restrict__ qWyl,
                    const uint32_t* __restrict__ qWgh, const uint32_t* __restrict__ qWgl,
                    const float* __restrict__ qby, const float* __restrict__ qbg,
                    float* __restrict__ qout,
                    const uint32_t* __restrict__ hXh, const uint32_t* __restrict__ hXl,
                    const uint32_t* __restrict__ hWyh, const uint32_t* __restrict__ hWyl,
                    const uint32_t* __restrict__ hWgh, const uint32_t* __restrict__ hWgl,
                    const float* __restrict__ hby, const float* __restrict__ hbg,
                    float* __restrict__ hout) {
    extern __shared__ char smem[];
    const uint32_t smem_base = (uint32_t)__cvta_generic_to_shared(smem);
    const int tid  = threadIdx.x;
    const int warp = tid >> 5;
    const int lane = tid & 31;
    const int n0 = blockIdx.x * TBN;

    const bool isq = (blockIdx.y < 5);
    const int m0 = isq ? blockIdx.y * TBM : (blockIdx.y - 5) * TBM;
    const uint32_t* Xh  = isq ? qXh  : hXh;
    const uint32_t* Xl  = isq ? qXl  : hXl;
    const uint32_t* Wyh = isq ? qWyh : hWyh;
    const uint32_t* Wyl = isq ? qWyl : hWyl;
    const uint32_t* Wgh = isq ? qWgh : hWgh;
    const uint32_t* Wgl = isq ? qWgl : hWgl;
    const float* by = isq ? qby : hby;
    const float* bg = isq ? qbg : hbg;
    float* out = isq ? qout : hout;

    // cp.async loader: one chunk = 6 regions x (128 rows x 128B), SW128 swizzle
    auto load_chunk = [&](int c) {
        const uint32_t bb = smem_base + SM_CTRL + (uint32_t)(c & 1) * CH_BYTES;
        const int kw0 = c * (TKC / 2);
#pragma unroll
        for (int i = 0; i < 24; i++) {
            const int reg = i >> 2;
            const int v   = tid + (i & 3) * 256;
            const int row = v >> 3, seg = v & 7;
            const uint32_t* s; int rb; uint32_t doff;
            if      (reg == 0) { s = Xh;  rb = m0; doff = 0; }
            else if (reg == 1) { s = Xl;  rb = m0; doff = 16384; }
            else if (reg == 2) { s = Wyh; rb = n0; doff = 32768; }
            else if (reg == 3) { s = Wyl; rb = n0; doff = 49152; }
            else if (reg == 4) { s = Wgh; rb = n0; doff = 65536; }
            else               { s = Wgl; rb = n0; doff = 81920; }
            const void* src = s + (size_t)(rb + row) * KW + kw0 + seg * 4;
            uint32_t bo = (uint32_t)(row * 128 + seg * 16);
            cpasync16(bb + doff + (bo ^ ((bo >> 3) & 0x70)), src);
        }
        asm volatile("cp.async.commit_group;" ::: "memory");
    };

#if USE_TC
    // ---------------- tcgen05 path ----------------
    const uint32_t mb0 = smem_base + 16, mb1 = smem_base + 24;
    if (warp == 0)
        asm volatile("tcgen05.alloc.cta_group::1.sync.aligned.shared::cta.b32 [%0], %1;"
                     :: "r"(smem_base), "r"(256u) : "memory");
    if (tid == 0) { mbar_init(mb0, 1); mbar_init(mb1, 1); }
    __syncthreads();
    uint32_t tmem;
    asm volatile("ld.shared.b32 %0, [%1];" : "=r"(tmem) : "r"(smem_base));
    const uint32_t tY = tmem, tG = tmem + 128;

    int ph0 = 0, ph1 = 0;
    for (int c = 0; c < NCHUNK; c++) {
        const int buf = c & 1;
        if (c >= 2) {
            if (buf) { mbar_wait(mb1, (uint32_t)ph1); ph1 ^= 1; }
            else     { mbar_wait(mb0, (uint32_t)ph0); ph0 ^= 1; }
        }
        load_chunk(c);
        asm volatile("cp.async.wait_group 0;" ::: "memory");
        asm volatile("tcgen05.fence::before_thread_sync;" ::: "memory");
        asm volatile("fence.proxy.async.shared::cta;" ::: "memory");
        __syncthreads();
        if (warp == 0) {
            asm volatile("tcgen05.fence::after_thread_sync;" ::: "memory");
            if (elect_one()) {
                const uint32_t bb = smem_base + SM_CTRL + (uint32_t)buf * CH_BYTES;
                uint64_t dAh = sdesc(bb),         dAl = sdesc(bb + 16384);
                uint64_t dYh = sdesc(bb + 32768), dYl = sdesc(bb + 49152);
                uint64_t dGh = sdesc(bb + 65536), dGl = sdesc(bb + 81920);
#pragma unroll
                for (int s = 0; s < 4; s++) {
                    uint64_t o = (uint64_t)(s * 2);
                    uint32_t en0 = (c == 0 && s == 0) ? 0u : 1u;
                    mma_ss(tY, dAh + o, dYh + o, IDESC_GG, en0);
                    mma_ss(tY, dAh + o, dYl + o, IDESC_GG, 1u);
                    mma_ss(tY, dAl + o, dYh + o, IDESC_GG, 1u);
                    mma_ss(tG, dAh + o, dGh + o, IDESC_GG, en0);
                    mma_ss(tG, dAh + o, dGl + o, IDESC_GG, 1u);
                    mma_ss(tG, dAl + o, dGh + o, IDESC_GG, 1u);
                }
                asm volatile(
                    "tcgen05.commit.cta_group::1.mbarrier::arrive::one.shared::cluster.b64 [%0];"
                    :: "r"(buf ? mb1 : mb0) : "memory");
            }
        }
    }
    mbar_wait(mb1, (uint32_t)ph1);
    asm volatile("tcgen05.fence::after_thread_sync;" ::: "memory");

    float* ep = (float*)(smem + SM_CTRL);
    if (warp < 4) {
        const int m = warp * 32 + lane;
#pragma unroll
        for (int s = 0; s < 4; s++) {
            uint32_t ry[32], rg[32];
            ldtm_x32(ry, tY + s * 32);
            ldtm_x32(rg, tG + s * 32);
            asm volatile("tcgen05.wait::ld.sync.aligned;" ::: "memory");
#pragma unroll
            for (int cc = 0; cc < 32; cc++) {
                int n = n0 + s * 32 + cc;
                float yv = __uint_as_float(ry[cc]) + by[n];
                float gv = __uint_as_float(rg[cc]) + bg[n];
                ep[m * 129 + s * 32 + cc] = tanhf(yv) * leaky(gv);
            }
        }
    }
    __syncthreads();
    for (int i = tid; i < TBM * TBN; i += 256) {
        int row = i >> 7, col = i & 127;
        out[(size_t)(m0 + row) * LSTM + n0 + col] = ep[row * 129 + col];
    }
    __syncthreads();
    if (tid == 0) { mbar_inval(mb0); mbar_inval(mb1); }
    __syncthreads();
    if (warp == 0) {
        asm volatile("tcgen05.relinquish_alloc_permit.cta_group::1.sync.aligned;");
        asm volatile("tcgen05.dealloc.cta_group::1.sync.aligned.b32 %0, %1;"
                     :: "r"(tmem), "r"(256u));
    }
#else
    // ---------------- legacy mma.m16n8k16 + ldmatrix ----------------
    // 8 warps: 2m x 4n, warp tile 64x32 (mt=4, nt=4)
    const int wm = (warp >> 2) * 64;
    const int wn = (warp & 3) * 32;

    // ldmatrix addressing (matches loader swizzle):
    //   word kw of row r sits at byte r*128 + ((kw*4) ^ ((r&7)<<4));
    //   aligned 16B group g of row r at byte r*128 + ((g ^ (r&7))<<4)
    // A x4: lanes 0-15 -> rows base+ (lane&15) @ k-half0; 16-31 same rows @ k-half1
    int rowA[4], swzA[4];
#pragma unroll
    for (int mt = 0; mt < 4; mt++) {
        rowA[mt] = wm + 16 * mt + (lane & 15);
        swzA[mt] = rowA[mt] & 7;
    }
    const int kselA = lane >> 4;           // 0/1
    // B x4: lanes 0-7 rows nb+0..7 @k0; 8-15 same @k1; 16-23 rows nb+8..15 @k0; 24-31 @k1
    int rowB[2], swzB[2];
#pragma unroll
    for (int ntp = 0; ntp < 2; ntp++) {
        rowB[ntp] = wn + 16 * ntp + (lane & 7) + ((lane & 16) >> 1);
        swzB[ntp] = rowB[ntp] & 7;
    }
    const int kselB = (lane >> 3) & 1;     // 0/1

    float accY[4][4][4] = {};
    float accG[4][4][4] = {};

    load_chunk(0);
    for (int c = 0; c < NCHUNK; c++) {
        if (c + 1 < NCHUNK) {
            load_chunk(c + 1);
            asm volatile("cp.async.wait_group 1;" ::: "memory");
        } else {
            asm volatile("cp.async.wait_group 0;" ::: "memory");
        }
        __syncthreads();
        const uint32_t bb = smem_base + SM_CTRL + (uint32_t)(c & 1) * CH_BYTES;

#pragma unroll
        for (int ks = 0; ks < 4; ks++) {
            const uint32_t gA = (uint32_t)(2 * ks + kselA);
            const uint32_t gB = (uint32_t)(2 * ks + kselB);
            // ---- A fragments (hi, lo) via ldmatrix.x4 ----
            uint32_t ah[4][4], al[4][4];
#pragma unroll
            for (int mt = 0; mt < 4; mt++) {
                uint32_t off = (uint32_t)(rowA[mt] * 128) + ((gA ^ (uint32_t)swzA[mt]) << 4);
                ldsm_x4(ah[mt][0], ah[mt][1], ah[mt][2], ah[mt][3], bb + off);
                ldsm_x4(al[mt][0], al[mt][1], al[mt][2], al[mt][3], bb + 16384 + off);
            }
            uint32_t offB[2];
#pragma unroll
            for (int ntp = 0; ntp < 2; ntp++)
                offB[ntp] = (uint32_t)(rowB[ntp] * 128) + ((gB ^ (uint32_t)swzB[ntp]) << 4);

            // ---- Y branch: B frags then 48 MMAs ----
            {
                uint32_t byh[4][2], byl[4][2];
#pragma unroll
                for (int ntp = 0; ntp < 2; ntp++) {
                    ldsm_x4(byh[2*ntp][0], byh[2*ntp][1], byh[2*ntp+1][0], byh[2*ntp+1][1],
                            bb + 32768 + offB[ntp]);
                    ldsm_x4(byl[2*ntp][0], byl[2*ntp][1], byl[2*ntp+1][0], byl[2*ntp+1][1],
                            bb + 49152 + offB[ntp]);
                }
#pragma unroll
                for (int nt = 0; nt < 4; nt++)
#pragma unroll
                    for (int mt = 0; mt < 4; mt++) {
                        mma_bf16(accY[mt][nt], al[mt], byh[nt][0], byh[nt][1]);
                        mma_bf16(accY[mt][nt], ah[mt], byl[nt][0], byl[nt][1]);
                        mma_bf16(accY[mt][nt], ah[mt], byh[nt][0], byh[nt][1]);
                    }
            }
            // ---- G branch ----
            {
                uint32_t bgh[4][2], bgl[4][2];
#pragma unroll
                for (int ntp = 0; ntp < 2; ntp++) {
                    ldsm_x4(bgh[2*ntp][0], bgh[2*ntp][1], bgh[2*ntp+1][0], bgh[2*ntp+1][1],
                            bb + 65536 + offB[ntp]);
                    ldsm_x4(bgl[2*ntp][0], bgl[2*ntp][1], bgl[2*ntp+1][0], bgl[2*ntp+1][1],
                            bb + 81920 + offB[ntp]);
                }
#pragma unroll
                for (int nt = 0; nt < 4; nt++)
#pragma unroll
                    for (int mt = 0; mt < 4; mt++) {
                        mma_bf16(accG[mt][nt], al[mt], bgh[nt][0], bgh[nt][1]);
                        mma_bf16(accG[mt][nt], ah[mt], bgl[nt][0], bgl[nt][1]);
                        mma_bf16(accG[mt][nt], ah[mt], bgh[nt][0], bgh[nt][1]);
                    }
            }
        }
        __syncthreads();
    }

    const int ar = lane >> 2;
    const int ac = lane & 3;
#pragma unroll
    for (int mt = 0; mt < 4; mt++) {
#pragma unroll
        for (int nt = 0; nt < 4; nt++) {
            int gr = m0 + wm + 16 * mt + ar;
            int gc = n0 + wn + 8 * nt + 2 * ac;
            float b_y0 = by[gc], b_y1 = by[gc + 1];
            float b_g0 = bg[gc], b_g1 = bg[gc + 1];
            float v00 = tanhf(accY[mt][nt][0] + b_y0) * leaky(accG[mt][nt][0] + b_g0);
            float v01 = tanhf(accY[mt][nt][1] + b_y1) * leaky(accG[mt][nt][1] + b_g1);
            float v10 = tanhf(accY[mt][nt][2] + b_y0) * leaky(accG[mt][nt][2] + b_g0);
            float v11 = tanhf(accY[mt][nt][3] + b_y1) * leaky(accG[mt][nt][3] + b_g1);
            *(float2*)&out[(size_t)gr * LSTM + gc]       = make_float2(v00, v01);
            *(float2*)&out[(size_t)(gr + 8) * LSTM + gc] = make_float2(v10, v11);
        }
    }
#endif
}

// ---------------------------------------------------------------------------
// Kernel 2: per-(b,r) attention block (proven)
// ---------------------------------------------------------------------------
#define CK 64
#define QS_STRIDE 65
#define HS_STRIDE 65
#define ATTN_SMEM_FLOATS (12000 + SL_Q * QS_STRIDE + SL_H * HS_STRIDE + SL_Q * SL_H)

__global__ __launch_bounds__(256)
void attn_kernel(const float* __restrict__ qf, const float* __restrict__ hf,
                 const float* __restrict__ emb, const float* __restrict__ notpad,
                 const float* __restrict__ cms, float* __restrict__ topic) {
    extern __shared__ float sm[];
    float* emb_s = sm;
    float* qs = emb_s + 12000;
    float* hs = qs + SL_Q * QS_STRIDE;
    float* S  = hs + SL_H * HS_STRIDE;

    const int t = threadIdx.x;
    const int r = blockIdx.x;
    const int b = blockIdx.y;
    const int br = b * NUM_R + r;

    for (int i = t; i < SL_H * WE; i += 256)
        emb_s[i] = emb[(size_t)br * (SL_H * WE) + i];

    const int q2 = t / 20;
    const int h2 = t % 20;
    float acc00 = 0.f, acc01 = 0.f, acc10 = 0.f, acc11 = 0.f;

    for (int kc = 0; kc < LSTM; kc += CK) {
        for (int i = t; i < SL_Q * CK; i += 256) {
            int row = i >> 6, col = i & 63;
            qs[row * QS_STRIDE + col] = qf[(size_t)(b * SL_Q + row) * LSTM + kc + col];
        }
        for (int i = t; i < SL_H * CK; i += 256) {
            int row = i >> 6, col = i & 63;
            hs[row * HS_STRIDE + col] = hf[(size_t)(br * SL_H + row) * LSTM + kc + col];
        }
        __syncthreads();
        if (t < 200) {
            const float* q0p = &qs[(2 * q2)     * QS_STRIDE];
            const float* q1p = &qs[(2 * q2 + 1) * QS_STRIDE];
            const float* h0p = &hs[(2 * h2)     * HS_STRIDE];
            const float* h1p = &hs[(2 * h2 + 1) * HS_STRIDE];
#pragma unroll 8
            for (int k = 0; k < CK; k++) {
                float q0 = q0p[k], q1 = q1p[k];
                float h0 = h0p[k], h1 = h1p[k];
                acc00 += q0 * h0; acc01 += q0 * h1;
                acc10 += q1 * h0; acc11 += q1 * h1;
            }
        }
        __syncthreads();
    }

    if (t < 200) {
        S[(2 * q2)     * SL_H + 2 * h2]     = acc00;
        S[(2 * q2)     * SL_H + 2 * h2 + 1] = acc01;
        S[(2 * q2 + 1) * SL_H + 2 * h2]     = acc10;
        S[(2 * q2 + 1) * SL_H + 2 * h2 + 1] = acc11;
    }
    __syncthreads();

    if (t < SL_Q) {
        float mx = -1e30f;
        for (int h = 0; h < SL_H; h++) {
            float m = notpad[(size_t)br * SL_H + h];
            float s = S[t * SL_H + h] * m + (m - 1.0f) * 10000.0f;
            S[t * SL_H + h] = s;
            mx = fmaxf(mx, s);
        }
        float den = 0.f;
        for (int h = 0; h < SL_H; h++) {
            float e = expf(S[t * SL_H + h] - mx);
            S[t * SL_H + h] = e;
            den += e;
        }
        float inv = 1.0f / den;
        for (int h = 0; h < SL_H; h++) S[t * SL_H + h] *= inv;
    }
    __syncthreads();

    const float c = cms[br];
    for (int o = t; o < SL_Q * WE; o += 256) {
        int q = o / WE, e = o % WE;
        float s = 0.f;
#pragma unroll 8
        for (int h = 0; h < SL_H; h++)
            s += S[q * SL_H + h] * emb_s[h * WE + e];
        topic[(size_t)(br * SL_Q + q) * WE + e] = s * c;
    }
}

// ---------------------------------------------------------------------------
// Kernel 3: feat = concat(q_embed, sum_r topic)
// ---------------------------------------------------------------------------
__global__ __launch_bounds__(256)
void feat_build(const float* __restrict__ q_embed, const float* __restrict__ topic,
                float* __restrict__ feat) {
    int idx = blockIdx.x * 256 + threadIdx.x;
    int m  = idx / FEATD;
    int e2 = idx % FEATD;
    float v;
    if (e2 < WE) {
        v = q_embed[(size_t)m * WE + e2];
    } else {
        int e = e2 - WE;
        int b = m / SL_Q, q = m % SL_Q;
        v = 0.f;
#pragma unroll
        for (int r = 0; r < NUM_R; r++)
            v += topic[(size_t)((b * NUM_R + r) * SL_Q + q) * WE + e];
    }
    feat[idx] = v;
}

// ---------------------------------------------------------------------------
// Kernel 4: out = sigmoid(feat@Wg + bg) * feat
// ---------------------------------------------------------------------------
#define FBM 64
#define FBN 64
#define FBK 16

__global__ __launch_bounds__(256)
void final_gemm(const float* __restrict__ feat, const float* __restrict__ Wg,
                const float* __restrict__ bg, float* __restrict__ out) {
    __shared__ float Fs[FBM][FBK + 1];
    __shared__ float Bsm[FBK][FBN + 1];

    const int t = threadIdx.x;
    const int ty = t >> 4, tx = t & 15;
    const int m0 = blockIdx.x * FBM;
    const int n0 = blockIdx.y * FBN;

    float acc[4][4];
#pragma unroll
    for (int i = 0; i < 4; i++)
#pragma unroll
        for (int j = 0; j < 4; j++) acc[i][j] = 0.f;

    for (int k0 = 0; k0 < FEATD; k0 += FBK) {
        for (int i = t; i < FBM * FBK; i += 256) {
            int r = i >> 4, c = i & 15;
            int k = k0 + c;
            Fs[r][c] = (k < FEATD) ? feat[(size_t)(m0 + r) * FEATD + k] : 0.f;
        }
        for (int i = t; i < FBK * FBN; i += 256) {
            int r = i >> 6, c = i & 63;
            int k = k0 + r, n = n0 + c;
            Bsm[r][c] = (k < FEATD && n < FEATD) ? Wg[(size_t)k * FEATD + n] : 0.f;
        }
        __syncthreads();
#pragma unroll
        for (int k = 0; k < FBK; k++) {
            float a[4], bb[4];
#pragma unroll
            for (int i = 0; i < 4; i++) a[i]  = Fs[ty * 4 + i][k];
#pragma unroll
            for (int j = 0; j < 4; j++) bb[j] = Bsm[k][tx * 4 + j];
#pragma unroll
            for (int i = 0; i < 4; i++)
#pragma unroll
                for (int j = 0; j < 4; j++) acc[i][j] += a[i] * bb[j];
        }
        __syncthreads();
    }

#pragma unroll
    for (int i = 0; i < 4; i++) {
        int row = m0 + ty * 4 + i;
#pragma unroll
        for (int j = 0; j < 4; j++) {
            int col = n0 + tx * 4 + j;
            if (col < FEATD) {
                float v = acc[i][j] + bg[col];
                float g = 1.0f / (1.0f + expf(-v));
                out[(size_t)row * FEATD + col] = g * feat[(size_t)row * FEATD + col];
            }
        }
    }
}

// ---------------------------------------------------------------------------
// Host launcher
// ---------------------------------------------------------------------------
extern "C" void kernel_launch(void* const* d_in, const int* in_sizes, int n_in,
                              void* d_out, int out_size) {
    const float* q_embed = (const float*)d_in[0];
    const float* q_enc   = (const float*)d_in[1];
    const float* h_embed = (const float*)d_in[2];
    const float* h_enc   = (const float*)d_in[3];
    const float* notpad  = (const float*)d_in[4];
    const float* cms     = (const float*)d_in[5];
    const float* Wq_y = (const float*)d_in[6];
    const float* bq_y = (const float*)d_in[7];
    const float* Wq_g = (const float*)d_in[8];
    const float* bq_g = (const float*)d_in[9];
    const float* Wh_y = (const float*)d_in[10];
    const float* bh_y = (const float*)d_in[11];
    const float* Wh_g = (const float*)d_in[12];
    const float* bh_g = (const float*)d_in[13];
    const float* Wg   = (const float*)d_in[14];
    const float* bg   = (const float*)d_in[15];
    float* out = (float*)d_out;

    float *qf, *hf, *topic, *feat;
    cudaGetSymbolAddress((void**)&qf,    g_qfeat);
    cudaGetSymbolAddress((void**)&hf,    g_hfeat);
    cudaGetSymbolAddress((void**)&topic, g_topic);
    cudaGetSymbolAddress((void**)&feat,  g_feat);

    uint32_t *xq_h, *xq_l, *xh_h, *xh_l;
    uint32_t *wqy_h, *wqy_l, *wqg_h, *wqg_l, *why_h, *why_l, *whg_h, *whg_l;
    cudaGetSymbolAddress((void**)&xq_h, g_xq_h);
    cudaGetSymbolAddress((void**)&xq_l, g_xq_l);
    cudaGetSymbolAddress((void**)&xh_h, g_xh_h);
    cudaGetSymbolAddress((void**)&xh_l, g_xh_l);
    cudaGetSymbolAddress((void**)&wqy_h, g_wqy_h);
    cudaGetSymbolAddress((void**)&wqy_l, g_wqy_l);
    cudaGetSymbolAddress((void**)&wqg_h, g_wqg_h);
    cudaGetSymbolAddress((void**)&wqg_l, g_wqg_l);
    cudaGetSymbolAddress((void**)&why_h, g_why_h);
    cudaGetSymbolAddress((void**)&why_l, g_why_l);
    cudaGetSymbolAddress((void**)&whg_h, g_whg_h);
    cudaGetSymbolAddress((void**)&whg_l, g_whg_l);

    cudaFuncSetAttribute(gated_gemm_all, cudaFuncAttributeMaxDynamicSharedMemorySize,
                         GG_SMEM);
    const int attn_smem = ATTN_SMEM_FLOATS * (int)sizeof(float);
    cudaFuncSetAttribute(attn_kernel, cudaFuncAttributeMaxDynamicSharedMemorySize,
                         attn_smem);

    // launch 0: fused X splits
    {
        int n4 = (MQ + MH) * BILSTM / 4;
        split_x_all<<<(n4 + 255) / 256, 256>>>(q_enc, xq_h, xq_l, h_enc, xh_h, xh_l);
    }
    // launch 1: fused W transposed splits
    {
        dim3 wg(BILSTM / 32, LSTM / 32, 4);
        split_wt_all<<<wg, 256>>>(Wq_y, wqy_h, wqy_l, Wq_g, wqg_h, wqg_l,
                                  Wh_y, why_h, why_l, Wh_g, whg_h, whg_l);
    }
    // launches 2-4: padding so ncu -s 5 captures the gemm
    nop_kernel<<<1, 32>>>();
    nop_kernel<<<1, 32>>>();
    nop_kernel<<<1, 32>>>();

    // launch 5: merged gated transforms (q tiles 0-4, h tiles 5-104)
    gated_gemm_all<<<dim3(LSTM / TBN, 5 + MH / TBM), 256, GG_SMEM>>>(
        xq_h, xq_l, wqy_h, wqy_l, wqg_h, wqg_l, bq_y, bq_g, qf,
        xh_h, xh_l, why_h, why_l, whg_h, whg_l, bh_y, bh_g, hf);

    // launch 6: attention + topic
    attn_kernel<<<dim3(NUM_R, BS), 256, attn_smem>>>(qf, hf, h_embed, notpad, cms, topic);

    // launch 7: concat + reduce over r
    feat_build<<<(MQ * FEATD) / 256, 256>>>(q_embed, topic, feat);

    // launch 8: final gated output
    final_gemm<<<dim3(MQ / FBM, (FEATD + FBN - 1) / FBN), 256>>>(feat, Wg, bg, out);
}